// round 1
// baseline (speedup 1.0000x reference)
#include <cuda_runtime.h>
#include <math.h>

#define EMBED 768
#define NHEAD 12
#define HDIM  64
#define BB    4
#define NN    2048
#define MTOT  (BB * NN)          // 8192
#define QKVW  (3 * EMBED)        // 2304

// Scratch (allocation-free rule: __device__ globals)
__device__ float g_qkv[(size_t)MTOT * QKVW];   // [B*N, 3*768] : Q|K|V per row
__device__ float g_ctx[(size_t)MTOT * EMBED];  // attention output, [b,n,h,d] packed

// ---------------------------------------------------------------------------
// 16-lane-group butterfly reductions (rows of the S tile live on 16 lanes)
// ---------------------------------------------------------------------------
__device__ __forceinline__ float rmax16(float v) {
#pragma unroll
    for (int o = 8; o; o >>= 1) v = fmaxf(v, __shfl_xor_sync(0xffffffffu, v, o));
    return v;
}
__device__ __forceinline__ float rsum16(float v) {
#pragma unroll
    for (int o = 8; o; o >>= 1) v += __shfl_xor_sync(0xffffffffu, v, o);
    return v;
}

// ---------------------------------------------------------------------------
// SGEMM (NT): C[M][Nn] = A[M][K] @ B[Nn][K]^T + bias[Nn]
// Block tile 64x64, K-tile 16, 256 threads, 4x4 micro-tile per thread.
// A, B loaded transposed into smem (k-major) so the inner loop is rank-1
// updates with float4 smem reads (conflict-free with +4 pad).
// ---------------------------------------------------------------------------
__global__ __launch_bounds__(256) void sgemm64_nt_bias(
    const float* __restrict__ A, const float* __restrict__ B,
    const float* __restrict__ bias, float* __restrict__ C,
    int M, int Nn, int K)
{
    __shared__ float As[16][68];
    __shared__ float Bs[16][68];

    const int tid = threadIdx.x;
    const int tx = tid & 15;          // 0..15 -> N micro-tile
    const int ty = tid >> 4;          // 0..15 -> M micro-tile
    const int n0 = blockIdx.x * 64;
    const int m0 = blockIdx.y * 64;

    const int lrow = tid >> 2;        // 0..63
    const int lk   = (tid & 3) * 4;   // 0,4,8,12

    float acc[4][4];
#pragma unroll
    for (int i = 0; i < 4; ++i)
#pragma unroll
        for (int j = 0; j < 4; ++j) acc[i][j] = 0.0f;

    for (int k0 = 0; k0 < K; k0 += 16) {
        float4 av = *(const float4*)(A + (size_t)(m0 + lrow) * K + k0 + lk);
        float4 bv = *(const float4*)(B + (size_t)(n0 + lrow) * K + k0 + lk);
        __syncthreads();
        As[lk + 0][lrow] = av.x; As[lk + 1][lrow] = av.y;
        As[lk + 2][lrow] = av.z; As[lk + 3][lrow] = av.w;
        Bs[lk + 0][lrow] = bv.x; Bs[lk + 1][lrow] = bv.y;
        Bs[lk + 2][lrow] = bv.z; Bs[lk + 3][lrow] = bv.w;
        __syncthreads();
#pragma unroll
        for (int kk = 0; kk < 16; ++kk) {
            float4 a4 = *(const float4*)&As[kk][ty * 4];
            float4 b4 = *(const float4*)&Bs[kk][tx * 4];
            float a[4] = {a4.x, a4.y, a4.z, a4.w};
            float b[4] = {b4.x, b4.y, b4.z, b4.w};
#pragma unroll
            for (int i = 0; i < 4; ++i)
#pragma unroll
                for (int j = 0; j < 4; ++j) acc[i][j] += a[i] * b[j];
        }
    }

    float4 bi4 = *(const float4*)(bias + n0 + tx * 4);
    float bb[4] = {bi4.x, bi4.y, bi4.z, bi4.w};
#pragma unroll
    for (int i = 0; i < 4; ++i) {
        float4 o;
        o.x = acc[i][0] + bb[0];
        o.y = acc[i][1] + bb[1];
        o.z = acc[i][2] + bb[2];
        o.w = acc[i][3] + bb[3];
        *(float4*)(C + (size_t)(m0 + ty * 4 + i) * Nn + n0 + tx * 4) = o;
    }
}

// ---------------------------------------------------------------------------
// Flash-attention (fp32): one block = 64 queries of one (b,h).
// BM=64, BN=64, D=64, 256 threads, 4x4 micro-tiles, online softmax.
// smem: Qt[d][q], Kt[d][k] (k-major for QK^T), Vs[k][d], Ps[q][k]. 68-pad.
// Dynamic smem = 4 * 64 * 68 * 4 = 69632 bytes.
// ---------------------------------------------------------------------------
__global__ __launch_bounds__(256) void attn_flash64()
{
    extern __shared__ float smem[];
    float (*Qt)[68] = (float(*)[68])(smem);
    float (*Kt)[68] = (float(*)[68])(smem + 64 * 68);
    float (*Vs)[68] = (float(*)[68])(smem + 2 * 64 * 68);
    float (*Ps)[68] = (float(*)[68])(smem + 3 * 64 * 68);

    const int tid = threadIdx.x;
    const int tx = tid & 15;
    const int ty = tid >> 4;
    const int b = blockIdx.y / NHEAD;
    const int h = blockIdx.y % NHEAD;
    const int q0 = blockIdx.x * 64;

    const int lrow = tid >> 2;         // 0..63
    const int lseg = (tid & 3) * 16;   // 0,16,32,48

    // Load Q tile transposed: Qt[d][qrow]
    {
        const float* src = g_qkv + ((size_t)(b * NN + q0 + lrow)) * QKVW + h * HDIM + lseg;
#pragma unroll
        for (int u = 0; u < 4; ++u) {
            float4 v = *(const float4*)(src + u * 4);
            Qt[lseg + u * 4 + 0][lrow] = v.x;
            Qt[lseg + u * 4 + 1][lrow] = v.y;
            Qt[lseg + u * 4 + 2][lrow] = v.z;
            Qt[lseg + u * 4 + 3][lrow] = v.w;
        }
    }

    float mr[4], lr[4], oa[4][4];
#pragma unroll
    for (int i = 0; i < 4; ++i) {
        mr[i] = -3.0e38f;
        lr[i] = 0.0f;
#pragma unroll
        for (int j = 0; j < 4; ++j) oa[i][j] = 0.0f;
    }

    const float scale = 0.125f;  // 1/sqrt(64)

    for (int kt = 0; kt < NN / 64; ++kt) {
        __syncthreads();  // protect previous iteration's Kt/Vs/Ps reads
        // Load K transposed (Kt[d][key]) and V direct (Vs[key][d])
        {
            const size_t rowbase = (size_t)(b * NN + kt * 64 + lrow) * QKVW + h * HDIM + lseg;
            const float* srck = g_qkv + rowbase + EMBED;       // K at offset 768
            const float* srcv = g_qkv + rowbase + 2 * EMBED;   // V at offset 1536
#pragma unroll
            for (int u = 0; u < 4; ++u) {
                float4 v = *(const float4*)(srck + u * 4);
                Kt[lseg + u * 4 + 0][lrow] = v.x;
                Kt[lseg + u * 4 + 1][lrow] = v.y;
                Kt[lseg + u * 4 + 2][lrow] = v.z;
                Kt[lseg + u * 4 + 3][lrow] = v.w;
                float4 w = *(const float4*)(srcv + u * 4);
                *(float4*)&Vs[lrow][lseg + u * 4] = w;
            }
        }
        __syncthreads();

        // S = Q @ K^T (4x4 per thread, rank-1 over d)
        float s[4][4];
#pragma unroll
        for (int i = 0; i < 4; ++i)
#pragma unroll
            for (int j = 0; j < 4; ++j) s[i][j] = 0.0f;
#pragma unroll 16
        for (int d = 0; d < 64; ++d) {
            float4 a4 = *(const float4*)&Qt[d][ty * 4];
            float4 b4 = *(const float4*)&Kt[d][tx * 4];
            float a[4] = {a4.x, a4.y, a4.z, a4.w};
            float bb2[4] = {b4.x, b4.y, b4.z, b4.w};
#pragma unroll
            for (int i = 0; i < 4; ++i)
#pragma unroll
                for (int j = 0; j < 4; ++j) s[i][j] += a[i] * bb2[j];
        }

        // Online softmax per row (row lives on 16 lanes)
#pragma unroll
        for (int i = 0; i < 4; ++i) {
#pragma unroll
            for (int j = 0; j < 4; ++j) s[i][j] *= scale;
            float rm = fmaxf(fmaxf(s[i][0], s[i][1]), fmaxf(s[i][2], s[i][3]));
            rm = rmax16(rm);
            float mn = fmaxf(mr[i], rm);
            float alpha = __expf(mr[i] - mn);
            mr[i] = mn;
            float ps = 0.0f;
#pragma unroll
            for (int j = 0; j < 4; ++j) {
                s[i][j] = __expf(s[i][j] - mn);
                ps += s[i][j];
            }
            ps = rsum16(ps);
            lr[i] = lr[i] * alpha + ps;
#pragma unroll
            for (int j = 0; j < 4; ++j) oa[i][j] *= alpha;
            *(float4*)&Ps[ty * 4 + i][tx * 4] = make_float4(s[i][0], s[i][1], s[i][2], s[i][3]);
        }
        __syncthreads();

        // O += P @ V (rank-1 over key index c)
#pragma unroll 16
        for (int c = 0; c < 64; ++c) {
            float a[4];
#pragma unroll
            for (int i = 0; i < 4; ++i) a[i] = Ps[ty * 4 + i][c];
            float4 b4 = *(const float4*)&Vs[c][tx * 4];
            float bb2[4] = {b4.x, b4.y, b4.z, b4.w};
#pragma unroll
            for (int i = 0; i < 4; ++i)
#pragma unroll
                for (int j = 0; j < 4; ++j) oa[i][j] += a[i] * bb2[j];
        }
    }

    // Normalize and write ctx[b, q, h, d]
    float* dst = g_ctx + ((size_t)(b * NN + q0)) * EMBED + h * HDIM;
#pragma unroll
    for (int i = 0; i < 4; ++i) {
        float inv = 1.0f / lr[i];
        float4 o;
        o.x = oa[i][0] * inv;
        o.y = oa[i][1] * inv;
        o.z = oa[i][2] * inv;
        o.w = oa[i][3] * inv;
        *(float4*)(dst + (size_t)(ty * 4 + i) * EMBED + tx * 4) = o;
    }
}

// ---------------------------------------------------------------------------
extern "C" void kernel_launch(void* const* d_in, const int* in_sizes, int n_in,
                              void* d_out, int out_size)
{
    (void)in_sizes; (void)n_in; (void)out_size;
    const float* x     = (const float*)d_in[0];
    const float* w_qkv = (const float*)d_in[1];
    const float* b_qkv = (const float*)d_in[2];
    const float* w_out = (const float*)d_in[3];
    const float* b_out = (const float*)d_in[4];
    float* out = (float*)d_out;

    float* qkv_p; float* ctx_p;
    cudaGetSymbolAddress((void**)&qkv_p, g_qkv);
    cudaGetSymbolAddress((void**)&ctx_p, g_ctx);

    // 1) QKV projection: [8192,768] x [2304,768]^T
    {
        dim3 grid(QKVW / 64, MTOT / 64);
        sgemm64_nt_bias<<<grid, 256>>>(x, w_qkv, b_qkv, qkv_p, MTOT, QKVW, EMBED);
    }

    // 2) Flash attention
    {
        static int smem_set = 0;
        const int smem_bytes = 4 * 64 * 68 * (int)sizeof(float);  // 69632
        if (!smem_set) {
            cudaFuncSetAttribute(attn_flash64,
                                 cudaFuncAttributeMaxDynamicSharedMemorySize, smem_bytes);
            smem_set = 1;
        }
        dim3 grid(NN / 64, BB * NHEAD);
        attn_flash64<<<grid, 256, smem_bytes>>>();
    }

    // 3) Output projection: [8192,768] x [768,768]^T
    {
        dim3 grid(EMBED / 64, MTOT / 64);
        sgemm64_nt_bias<<<grid, 256>>>(ctx_p, w_out, b_out, out, MTOT, EMBED, EMBED);
    }
}

// round 2
// speedup vs baseline: 1.9224x; 1.9224x over previous
#include <cuda_runtime.h>
#include <math.h>

#define EMBED 768
#define NHEAD 12
#define HDIM  64
#define BB    4
#define NN    2048
#define MTOT  (BB * NN)          // 8192
#define QKVW  (3 * EMBED)        // 2304

// Scratch (allocation-free rule: __device__ globals)
__device__ float g_qkv[(size_t)MTOT * QKVW];   // [B*N, 3*768] : Q|K|V per row
__device__ float g_ctx[(size_t)MTOT * EMBED];  // attention output, [b,n,h,d] packed

// ---------------------------------------------------------------------------
// tf32 helpers
// ---------------------------------------------------------------------------
__device__ __forceinline__ unsigned f2tf(float f) {
    unsigned u;
    asm("cvt.rna.tf32.f32 %0, %1;" : "=r"(u) : "f"(f));
    return u;
}

__device__ __forceinline__ void mma_tf32(float c[4],
                                         unsigned a0, unsigned a1, unsigned a2, unsigned a3,
                                         unsigned b0, unsigned b1) {
    asm volatile(
        "mma.sync.aligned.m16n8k8.row.col.f32.tf32.tf32.f32 "
        "{%0,%1,%2,%3}, {%4,%5,%6,%7}, {%8,%9}, {%0,%1,%2,%3};"
        : "+f"(c[0]), "+f"(c[1]), "+f"(c[2]), "+f"(c[3])
        : "r"(a0), "r"(a1), "r"(a2), "r"(a3), "r"(b0), "r"(b1));
}

// ---------------------------------------------------------------------------
// tf32 GEMM (NT): C[M][Nn] = A[M][K] @ B[Nn][K]^T + bias
// 128x128 block tile, BK=16, 256 threads (8 warps), warp tile 64x32.
// Smem row stride 20 words -> conflict-free fragment LDS.
// ---------------------------------------------------------------------------
__global__ __launch_bounds__(256) void gemm_tf32_nt_bias(
    const float* __restrict__ A, const float* __restrict__ B,
    const float* __restrict__ bias, float* __restrict__ C,
    int M, int Nn, int K)
{
    __shared__ unsigned As[128][20];
    __shared__ unsigned Bs[128][20];

    const int tid  = threadIdx.x;
    const int lane = tid & 31;
    const int warp = tid >> 5;
    const int gid  = lane >> 2;   // 0..7
    const int tig  = lane & 3;    // 0..3

    const int wm = (warp >> 2) * 64;   // 0 or 64
    const int wn = (warp & 3) * 32;    // 0,32,64,96

    const int n0 = blockIdx.x * 128;
    const int m0 = blockIdx.y * 128;

    const int lrow = tid >> 1;         // 0..127
    const int lk   = (tid & 1) * 8;    // 0 or 8

    float acc[4][4][4];
#pragma unroll
    for (int mi = 0; mi < 4; ++mi)
#pragma unroll
        for (int ni = 0; ni < 4; ++ni)
#pragma unroll
            for (int r = 0; r < 4; ++r) acc[mi][ni][r] = 0.0f;

    const float* Arow = A + (size_t)(m0 + lrow) * K + lk;
    const float* Brow = B + (size_t)(n0 + lrow) * K + lk;

    for (int k0 = 0; k0 < K; k0 += 16) {
        float4 a0v = *(const float4*)(Arow + k0);
        float4 a1v = *(const float4*)(Arow + k0 + 4);
        float4 b0v = *(const float4*)(Brow + k0);
        float4 b1v = *(const float4*)(Brow + k0 + 4);
        __syncthreads();
        As[lrow][lk + 0] = f2tf(a0v.x); As[lrow][lk + 1] = f2tf(a0v.y);
        As[lrow][lk + 2] = f2tf(a0v.z); As[lrow][lk + 3] = f2tf(a0v.w);
        As[lrow][lk + 4] = f2tf(a1v.x); As[lrow][lk + 5] = f2tf(a1v.y);
        As[lrow][lk + 6] = f2tf(a1v.z); As[lrow][lk + 7] = f2tf(a1v.w);
        Bs[lrow][lk + 0] = f2tf(b0v.x); Bs[lrow][lk + 1] = f2tf(b0v.y);
        Bs[lrow][lk + 2] = f2tf(b0v.z); Bs[lrow][lk + 3] = f2tf(b0v.w);
        Bs[lrow][lk + 4] = f2tf(b1v.x); Bs[lrow][lk + 5] = f2tf(b1v.y);
        Bs[lrow][lk + 6] = f2tf(b1v.z); Bs[lrow][lk + 7] = f2tf(b1v.w);
        __syncthreads();

#pragma unroll
        for (int ks = 0; ks < 2; ++ks) {
            const int kk = ks * 8;
            unsigned af[4][4];
#pragma unroll
            for (int mi = 0; mi < 4; ++mi) {
                const int r = wm + mi * 16 + gid;
                af[mi][0] = As[r][kk + tig];
                af[mi][1] = As[r + 8][kk + tig];
                af[mi][2] = As[r][kk + tig + 4];
                af[mi][3] = As[r + 8][kk + tig + 4];
            }
            unsigned bf[4][2];
#pragma unroll
            for (int ni = 0; ni < 4; ++ni) {
                const int r = wn + ni * 8 + gid;
                bf[ni][0] = Bs[r][kk + tig];
                bf[ni][1] = Bs[r][kk + tig + 4];
            }
#pragma unroll
            for (int mi = 0; mi < 4; ++mi)
#pragma unroll
                for (int ni = 0; ni < 4; ++ni)
                    mma_tf32(acc[mi][ni], af[mi][0], af[mi][1], af[mi][2], af[mi][3],
                             bf[ni][0], bf[ni][1]);
        }
    }

    // Epilogue: bias + store (float2 per row-pair fragment)
#pragma unroll
    for (int ni = 0; ni < 4; ++ni) {
        const int col = n0 + wn + ni * 8 + 2 * tig;
        const float bx = bias[col];
        const float by = bias[col + 1];
#pragma unroll
        for (int mi = 0; mi < 4; ++mi) {
            const int row = m0 + wm + mi * 16 + gid;
            float2 v0 = make_float2(acc[mi][ni][0] + bx, acc[mi][ni][1] + by);
            float2 v1 = make_float2(acc[mi][ni][2] + bx, acc[mi][ni][3] + by);
            *(float2*)(C + (size_t)row * Nn + col) = v0;
            *(float2*)(C + (size_t)(row + 8) * Nn + col) = v1;
        }
    }
}

// ---------------------------------------------------------------------------
// Flash attention with tf32 MMA.
// Block: 64 queries of one (b,h), 128 threads (4 warps x 16 query rows).
// Smem (dynamic, 69632B): Qs[64][68], Ks[64][68], Vt[64][68], Ps[64][68]
// Qs: [q][d] (A operand), Ks: [key][d] (B col-major), Vt: [d][key] (B),
// Ps: [q][key] (A operand of PV).
// ---------------------------------------------------------------------------
__global__ __launch_bounds__(128) void attn_flash_tf32()
{
    extern __shared__ unsigned sm[];
    unsigned (*Qs)[68] = (unsigned(*)[68])(sm);
    unsigned (*Ks)[68] = (unsigned(*)[68])(sm + 64 * 68);
    unsigned (*Vt)[68] = (unsigned(*)[68])(sm + 2 * 64 * 68);
    unsigned (*Ps)[68] = (unsigned(*)[68])(sm + 3 * 64 * 68);

    const int tid  = threadIdx.x;
    const int lane = tid & 31;
    const int warp = tid >> 5;
    const int gid  = lane >> 2;
    const int tig  = lane & 3;
    const int wm   = warp * 16;

    const int b  = blockIdx.y / NHEAD;
    const int h  = blockIdx.y % NHEAD;
    const int q0 = blockIdx.x * 64;

    const int lrow  = tid & 63;          // 0..63
    const int dhalf = (tid >> 6) * 32;   // 0 or 32

    // Load Q tile: Qs[q][d]
    {
        const float* src = g_qkv + (size_t)(b * NN + q0 + lrow) * QKVW + h * HDIM + dhalf;
#pragma unroll
        for (int u = 0; u < 8; ++u) {
            float4 v = *(const float4*)(src + u * 4);
            Qs[lrow][dhalf + u * 4 + 0] = f2tf(v.x);
            Qs[lrow][dhalf + u * 4 + 1] = f2tf(v.y);
            Qs[lrow][dhalf + u * 4 + 2] = f2tf(v.z);
            Qs[lrow][dhalf + u * 4 + 3] = f2tf(v.w);
        }
    }

    float m0r = -1.0e30f, m1r = -1.0e30f;
    float l0 = 0.0f, l1 = 0.0f;
    float O[8][4];
#pragma unroll
    for (int ni = 0; ni < 8; ++ni)
#pragma unroll
        for (int r = 0; r < 4; ++r) O[ni][r] = 0.0f;

    const float scale = 0.125f;  // 1/sqrt(64)

    for (int kt = 0; kt < NN / 64; ++kt) {
        __syncthreads();  // prev iteration's Ks/Vt reads complete
        // Load K: Ks[key][d];  V transposed: Vt[d][key]
        {
            const size_t rb = (size_t)(b * NN + kt * 64 + lrow) * QKVW + h * HDIM + dhalf;
            const float* srck = g_qkv + rb + EMBED;
            const float* srcv = g_qkv + rb + 2 * EMBED;
#pragma unroll
            for (int u = 0; u < 8; ++u) {
                float4 v = *(const float4*)(srck + u * 4);
                Ks[lrow][dhalf + u * 4 + 0] = f2tf(v.x);
                Ks[lrow][dhalf + u * 4 + 1] = f2tf(v.y);
                Ks[lrow][dhalf + u * 4 + 2] = f2tf(v.z);
                Ks[lrow][dhalf + u * 4 + 3] = f2tf(v.w);
                float4 w = *(const float4*)(srcv + u * 4);
                Vt[dhalf + u * 4 + 0][lrow] = f2tf(w.x);
                Vt[dhalf + u * 4 + 1][lrow] = f2tf(w.y);
                Vt[dhalf + u * 4 + 2][lrow] = f2tf(w.z);
                Vt[dhalf + u * 4 + 3][lrow] = f2tf(w.w);
            }
        }
        __syncthreads();

        // S = Q @ K^T : warp's 16 rows x 64 keys
        float s[8][4];
#pragma unroll
        for (int ni = 0; ni < 8; ++ni)
#pragma unroll
            for (int r = 0; r < 4; ++r) s[ni][r] = 0.0f;

#pragma unroll
        for (int ks = 0; ks < 8; ++ks) {
            const int kk = ks * 8;
            const unsigned a0 = Qs[wm + gid][kk + tig];
            const unsigned a1 = Qs[wm + gid + 8][kk + tig];
            const unsigned a2 = Qs[wm + gid][kk + tig + 4];
            const unsigned a3 = Qs[wm + gid + 8][kk + tig + 4];
#pragma unroll
            for (int ni = 0; ni < 8; ++ni) {
                const unsigned b0 = Ks[ni * 8 + gid][kk + tig];
                const unsigned b1 = Ks[ni * 8 + gid][kk + tig + 4];
                mma_tf32(s[ni], a0, a1, a2, a3, b0, b1);
            }
        }

        // Online softmax (rows gid and gid+8 of this warp's band)
        float rm0 = -1.0e30f, rm1 = -1.0e30f;
#pragma unroll
        for (int ni = 0; ni < 8; ++ni) {
            s[ni][0] *= scale; s[ni][1] *= scale;
            s[ni][2] *= scale; s[ni][3] *= scale;
            rm0 = fmaxf(rm0, fmaxf(s[ni][0], s[ni][1]));
            rm1 = fmaxf(rm1, fmaxf(s[ni][2], s[ni][3]));
        }
        rm0 = fmaxf(rm0, __shfl_xor_sync(0xffffffffu, rm0, 1));
        rm0 = fmaxf(rm0, __shfl_xor_sync(0xffffffffu, rm0, 2));
        rm1 = fmaxf(rm1, __shfl_xor_sync(0xffffffffu, rm1, 1));
        rm1 = fmaxf(rm1, __shfl_xor_sync(0xffffffffu, rm1, 2));

        const float mn0 = fmaxf(m0r, rm0);
        const float mn1 = fmaxf(m1r, rm1);
        const float al0 = __expf(m0r - mn0);
        const float al1 = __expf(m1r - mn1);
        m0r = mn0; m1r = mn1;

        float ps0 = 0.0f, ps1 = 0.0f;
#pragma unroll
        for (int ni = 0; ni < 8; ++ni) {
            s[ni][0] = __expf(s[ni][0] - mn0);
            s[ni][1] = __expf(s[ni][1] - mn0);
            s[ni][2] = __expf(s[ni][2] - mn1);
            s[ni][3] = __expf(s[ni][3] - mn1);
            ps0 += s[ni][0] + s[ni][1];
            ps1 += s[ni][2] + s[ni][3];
            // store P (tf32) for the PV mma
            uint2 p0 = make_uint2(f2tf(s[ni][0]), f2tf(s[ni][1]));
            uint2 p1 = make_uint2(f2tf(s[ni][2]), f2tf(s[ni][3]));
            *(uint2*)&Ps[wm + gid][ni * 8 + 2 * tig] = p0;
            *(uint2*)&Ps[wm + gid + 8][ni * 8 + 2 * tig] = p1;
        }
        ps0 += __shfl_xor_sync(0xffffffffu, ps0, 1);
        ps0 += __shfl_xor_sync(0xffffffffu, ps0, 2);
        ps1 += __shfl_xor_sync(0xffffffffu, ps1, 1);
        ps1 += __shfl_xor_sync(0xffffffffu, ps1, 2);
        l0 = l0 * al0 + ps0;
        l1 = l1 * al1 + ps1;

#pragma unroll
        for (int ni = 0; ni < 8; ++ni) {
            O[ni][0] *= al0; O[ni][1] *= al0;
            O[ni][2] *= al1; O[ni][3] *= al1;
        }
        __syncwarp();

        // O += P @ V  (A = Ps rows of this warp, B = Vt)
#pragma unroll
        for (int ks = 0; ks < 8; ++ks) {
            const int kk = ks * 8;
            const unsigned a0 = Ps[wm + gid][kk + tig];
            const unsigned a1 = Ps[wm + gid + 8][kk + tig];
            const unsigned a2 = Ps[wm + gid][kk + tig + 4];
            const unsigned a3 = Ps[wm + gid + 8][kk + tig + 4];
#pragma unroll
            for (int ni = 0; ni < 8; ++ni) {
                const unsigned b0 = Vt[ni * 8 + gid][kk + tig];
                const unsigned b1 = Vt[ni * 8 + gid][kk + tig + 4];
                mma_tf32(O[ni], a0, a1, a2, a3, b0, b1);
            }
        }
    }

    // Normalize and write ctx[b, q, h, d]
    const float inv0 = 1.0f / l0;
    const float inv1 = 1.0f / l1;
    float* dst0 = g_ctx + (size_t)(b * NN + q0 + wm + gid) * EMBED + h * HDIM;
    float* dst1 = g_ctx + (size_t)(b * NN + q0 + wm + gid + 8) * EMBED + h * HDIM;
#pragma unroll
    for (int ni = 0; ni < 8; ++ni) {
        const int col = ni * 8 + 2 * tig;
        *(float2*)(dst0 + col) = make_float2(O[ni][0] * inv0, O[ni][1] * inv0);
        *(float2*)(dst1 + col) = make_float2(O[ni][2] * inv1, O[ni][3] * inv1);
    }
}

// ---------------------------------------------------------------------------
extern "C" void kernel_launch(void* const* d_in, const int* in_sizes, int n_in,
                              void* d_out, int out_size)
{
    (void)in_sizes; (void)n_in; (void)out_size;
    const float* x     = (const float*)d_in[0];
    const float* w_qkv = (const float*)d_in[1];
    const float* b_qkv = (const float*)d_in[2];
    const float* w_out = (const float*)d_in[3];
    const float* b_out = (const float*)d_in[4];
    float* out = (float*)d_out;

    float* qkv_p; float* ctx_p;
    cudaGetSymbolAddress((void**)&qkv_p, g_qkv);
    cudaGetSymbolAddress((void**)&ctx_p, g_ctx);

    // 1) QKV projection: [8192,768] x [2304,768]^T
    {
        dim3 grid(QKVW / 128, MTOT / 128);
        gemm_tf32_nt_bias<<<grid, 256>>>(x, w_qkv, b_qkv, qkv_p, MTOT, QKVW, EMBED);
    }

    // 2) Flash attention (tf32 mma)
    {
        static int smem_set = 0;
        const int smem_bytes = 4 * 64 * 68 * (int)sizeof(unsigned);  // 69632
        if (!smem_set) {
            cudaFuncSetAttribute(attn_flash_tf32,
                                 cudaFuncAttributeMaxDynamicSharedMemorySize, smem_bytes);
            smem_set = 1;
        }
        dim3 grid(NN / 64, BB * NHEAD);
        attn_flash_tf32<<<grid, 128, smem_bytes>>>();
    }

    // 3) Output projection: [8192,768] x [768,768]^T
    {
        dim3 grid(EMBED / 128, MTOT / 128);
        gemm_tf32_nt_bias<<<grid, 256>>>(ctx_p, w_out, b_out, out, MTOT, EMBED, EMBED);
    }
}

// round 3
// speedup vs baseline: 2.3462x; 1.2205x over previous
#include <cuda_runtime.h>
#include <math.h>

#define EMBED 768
#define NHEAD 12
#define HDIM  64
#define BB    4
#define NN    2048
#define MTOT  (BB * NN)          // 8192
#define QKVW  (3 * EMBED)        // 2304

// Scratch (allocation-free rule: __device__ globals)
__device__ float g_qkv[(size_t)MTOT * QKVW];   // [B*N, 3*768] : Q|K|V per row
__device__ float g_ctx[(size_t)MTOT * EMBED];  // attention output, [b,n,h,d] packed

// ---------------------------------------------------------------------------
// helpers
// ---------------------------------------------------------------------------
__device__ __forceinline__ unsigned f2tf(float f) {
    unsigned u;
    asm("cvt.rna.tf32.f32 %0, %1;" : "=r"(u) : "f"(f));
    return u;
}
__device__ __forceinline__ uint4 f2tf4(float4 v) {
    uint4 r;
    r.x = f2tf(v.x); r.y = f2tf(v.y); r.z = f2tf(v.z); r.w = f2tf(v.w);
    return r;
}
__device__ __forceinline__ float fexp2(float x) {
    float y;
    asm("ex2.approx.ftz.f32 %0, %1;" : "=f"(y) : "f"(x));
    return y;
}
__device__ __forceinline__ void mma_tf32(float c[4],
                                         unsigned a0, unsigned a1, unsigned a2, unsigned a3,
                                         unsigned b0, unsigned b1) {
    asm volatile(
        "mma.sync.aligned.m16n8k8.row.col.f32.tf32.tf32.f32 "
        "{%0,%1,%2,%3}, {%4,%5,%6,%7}, {%8,%9}, {%0,%1,%2,%3};"
        : "+f"(c[0]), "+f"(c[1]), "+f"(c[2]), "+f"(c[3])
        : "r"(a0), "r"(a1), "r"(a2), "r"(a3), "r"(b0), "r"(b1));
}

// ---------------------------------------------------------------------------
// tf32 GEMM (NT), double-buffered: C = A[M][K] @ B[Nn][K]^T + bias
// 128x128 block tile, BK=16, 256 threads (8 warps), warp tile 64x32.
// Smem row stride 36 words: STS.128 and fragment LDS both bank-conflict-free.
// Dynamic smem: 2 stages * 2 matrices * 128 * 36 * 4 = 73728 B.
// ---------------------------------------------------------------------------
#define GST (128 * 36)

__global__ __launch_bounds__(256, 2) void gemm_tf32_db(
    const float* __restrict__ A, const float* __restrict__ B,
    const float* __restrict__ bias, float* __restrict__ C,
    int M, int Nn, int K)
{
    extern __shared__ unsigned gs[];
    unsigned* Asm = gs;              // [2][128][36]
    unsigned* Bsm = gs + 2 * GST;    // [2][128][36]

    const int tid  = threadIdx.x;
    const int lane = tid & 31;
    const int warp = tid >> 5;
    const int gid  = lane >> 2;   // 0..7
    const int tig  = lane & 3;    // 0..3

    const int wm = (warp >> 2) * 64;   // 0 or 64
    const int wn = (warp & 3) * 32;    // 0,32,64,96

    const int n0 = blockIdx.x * 128;
    const int m0 = blockIdx.y * 128;

    const int lrow = tid >> 1;         // 0..127
    const int lk   = (tid & 1) * 8;    // 0 or 8

    float acc[4][4][4];
#pragma unroll
    for (int mi = 0; mi < 4; ++mi)
#pragma unroll
        for (int ni = 0; ni < 4; ++ni)
#pragma unroll
            for (int r = 0; r < 4; ++r) acc[mi][ni][r] = 0.0f;

    const float* Arow = A + (size_t)(m0 + lrow) * K + lk;
    const float* Brow = B + (size_t)(n0 + lrow) * K + lk;
    const int nT = K / 16;

    // prologue: tile 0 -> stage 0
    {
        float4 a0v = *(const float4*)(Arow);
        float4 a1v = *(const float4*)(Arow + 4);
        float4 b0v = *(const float4*)(Brow);
        float4 b1v = *(const float4*)(Brow + 4);
        *(uint4*)(Asm + lrow * 36 + lk)     = f2tf4(a0v);
        *(uint4*)(Asm + lrow * 36 + lk + 4) = f2tf4(a1v);
        *(uint4*)(Bsm + lrow * 36 + lk)     = f2tf4(b0v);
        *(uint4*)(Bsm + lrow * 36 + lk + 4) = f2tf4(b1v);
    }
    __syncthreads();

    for (int kt = 0; kt < nT; ++kt) {
        const int st = kt & 1;
        float4 a0v, a1v, b0v, b1v;
        if (kt + 1 < nT) {
            const int ko = (kt + 1) * 16;
            a0v = *(const float4*)(Arow + ko);
            a1v = *(const float4*)(Arow + ko + 4);
            b0v = *(const float4*)(Brow + ko);
            b1v = *(const float4*)(Brow + ko + 4);
        }

        const unsigned* Ast = Asm + st * GST;
        const unsigned* Bst = Bsm + st * GST;
#pragma unroll
        for (int ks = 0; ks < 2; ++ks) {
            const int kk = ks * 8;
            unsigned af[4][4];
#pragma unroll
            for (int mi = 0; mi < 4; ++mi) {
                const int r = wm + mi * 16 + gid;
                af[mi][0] = Ast[r * 36 + kk + tig];
                af[mi][1] = Ast[(r + 8) * 36 + kk + tig];
                af[mi][2] = Ast[r * 36 + kk + tig + 4];
                af[mi][3] = Ast[(r + 8) * 36 + kk + tig + 4];
            }
            unsigned bf[4][2];
#pragma unroll
            for (int ni = 0; ni < 4; ++ni) {
                const int r = wn + ni * 8 + gid;
                bf[ni][0] = Bst[r * 36 + kk + tig];
                bf[ni][1] = Bst[r * 36 + kk + tig + 4];
            }
#pragma unroll
            for (int mi = 0; mi < 4; ++mi)
#pragma unroll
                for (int ni = 0; ni < 4; ++ni)
                    mma_tf32(acc[mi][ni], af[mi][0], af[mi][1], af[mi][2], af[mi][3],
                             bf[ni][0], bf[ni][1]);
        }

        if (kt + 1 < nT) {
            unsigned* Ad = Asm + (st ^ 1) * GST;
            unsigned* Bd = Bsm + (st ^ 1) * GST;
            *(uint4*)(Ad + lrow * 36 + lk)     = f2tf4(a0v);
            *(uint4*)(Ad + lrow * 36 + lk + 4) = f2tf4(a1v);
            *(uint4*)(Bd + lrow * 36 + lk)     = f2tf4(b0v);
            *(uint4*)(Bd + lrow * 36 + lk + 4) = f2tf4(b1v);
            __syncthreads();
        }
    }

    // Epilogue: bias + store
#pragma unroll
    for (int ni = 0; ni < 4; ++ni) {
        const int col = n0 + wn + ni * 8 + 2 * tig;
        const float bx = bias[col];
        const float by = bias[col + 1];
#pragma unroll
        for (int mi = 0; mi < 4; ++mi) {
            const int row = m0 + wm + mi * 16 + gid;
            *(float2*)(C + (size_t)row * Nn + col) =
                make_float2(acc[mi][ni][0] + bx, acc[mi][ni][1] + by);
            *(float2*)(C + (size_t)(row + 8) * Nn + col) =
                make_float2(acc[mi][ni][2] + bx, acc[mi][ni][3] + by);
        }
    }
}

// ---------------------------------------------------------------------------
// Flash attention, tf32 MMA, Q-tile 128 / K-tile 64, 256 threads (8 warps),
// double-buffered K/V tiles.
// Smem (unsigned words): Qs[128][68] | Ks[2][64][68] | Vt[2][64][68] | Ps[128][68]
// total = 512*68*4 = 139264 B.
// Scale*log2(e) folded into Q; softmax uses ex2.approx.
// ---------------------------------------------------------------------------
#define AQS 0
#define AKS (128 * 68)
#define AVT (AKS + 2 * 64 * 68)
#define APS (AVT + 2 * 64 * 68)

__global__ __launch_bounds__(256) void attn_flash_tf32_v2()
{
    extern __shared__ unsigned sm[];

    const int tid  = threadIdx.x;
    const int lane = tid & 31;
    const int warp = tid >> 5;
    const int gid  = lane >> 2;
    const int tig  = lane & 3;
    const int wm   = warp * 16;

    const int b  = blockIdx.y / NHEAD;
    const int h  = blockIdx.y % NHEAD;
    const int q0 = blockIdx.x * 128;

    // ---- load Q tile (scaled into log2 domain) ----
    {
        const int qrow = tid & 127;
        const int qdh  = (tid >> 7) * 32;
        const float qs = 0.125f * 1.4426950408889634f;
        const float* src = g_qkv + (size_t)(b * NN + q0 + qrow) * QKVW + h * HDIM + qdh;
        unsigned* dst = sm + AQS + qrow * 68 + qdh;
#pragma unroll
        for (int u = 0; u < 8; ++u) {
            float4 v = *(const float4*)(src + u * 4);
            uint4 w;
            w.x = f2tf(v.x * qs); w.y = f2tf(v.y * qs);
            w.z = f2tf(v.z * qs); w.w = f2tf(v.w * qs);
            *(uint4*)(dst + u * 4) = w;
        }
    }

    // K/V loader mapping: r = row in tile, sel: 0,1 = K d-halves; 2,3 = V d-halves
    const int kr   = tid & 63;
    const int sel  = tid >> 6;
    const int kdh  = (sel & 1) * 32;
    const size_t kvoff = (size_t)h * HDIM + kdh + ((sel >> 1) ? 2 * EMBED : EMBED);

    float4 pf[8];
    // prologue: tile 0
    {
        const float* srcp = g_qkv + (size_t)(b * NN + kr) * QKVW + kvoff;
#pragma unroll
        for (int u = 0; u < 8; ++u) pf[u] = *(const float4*)(srcp + u * 4);
        if (sel < 2) {
            unsigned* dst = sm + AKS + kr * 68 + kdh;
#pragma unroll
            for (int u = 0; u < 8; ++u) *(uint4*)(dst + u * 4) = f2tf4(pf[u]);
        } else {
#pragma unroll
            for (int u = 0; u < 8; ++u) {
                unsigned* dc = sm + AVT + (kdh + u * 4) * 68 + kr;
                dc[0]       = f2tf(pf[u].x);
                dc[68]      = f2tf(pf[u].y);
                dc[2 * 68]  = f2tf(pf[u].z);
                dc[3 * 68]  = f2tf(pf[u].w);
            }
        }
    }
    __syncthreads();

    float m0r = -1.0e30f, m1r = -1.0e30f;
    float l0 = 0.0f, l1 = 0.0f;
    float O[8][4];
#pragma unroll
    for (int ni = 0; ni < 8; ++ni)
#pragma unroll
        for (int r = 0; r < 4; ++r) O[ni][r] = 0.0f;

    const int NT = NN / 64;
    for (int kt = 0; kt < NT; ++kt) {
        const int buf = kt & 1;
        // prefetch next K/V tile into regs
        if (kt + 1 < NT) {
            const float* srcp = g_qkv + (size_t)(b * NN + (kt + 1) * 64 + kr) * QKVW + kvoff;
#pragma unroll
            for (int u = 0; u < 8; ++u) pf[u] = *(const float4*)(srcp + u * 4);
        }

        const unsigned* Kst = sm + AKS + buf * 64 * 68;
        const unsigned* Vst = sm + AVT + buf * 64 * 68;
        const unsigned* Qw  = sm + AQS + (wm + gid) * 68;
        const unsigned* Qw8 = sm + AQS + (wm + gid + 8) * 68;

        // ---- S = Qhat @ K^T ----
        float s[8][4];
#pragma unroll
        for (int ni = 0; ni < 8; ++ni)
#pragma unroll
            for (int r = 0; r < 4; ++r) s[ni][r] = 0.0f;
#pragma unroll
        for (int ks = 0; ks < 8; ++ks) {
            const int kk = ks * 8;
            const unsigned a0 = Qw[kk + tig];
            const unsigned a1 = Qw8[kk + tig];
            const unsigned a2 = Qw[kk + tig + 4];
            const unsigned a3 = Qw8[kk + tig + 4];
#pragma unroll
            for (int ni = 0; ni < 8; ++ni) {
                const unsigned b0 = Kst[(ni * 8 + gid) * 68 + kk + tig];
                const unsigned b1 = Kst[(ni * 8 + gid) * 68 + kk + tig + 4];
                mma_tf32(s[ni], a0, a1, a2, a3, b0, b1);
            }
        }

        // ---- online softmax (log2 domain) ----
        float rm0 = -1.0e30f, rm1 = -1.0e30f;
#pragma unroll
        for (int ni = 0; ni < 8; ++ni) {
            rm0 = fmaxf(rm0, fmaxf(s[ni][0], s[ni][1]));
            rm1 = fmaxf(rm1, fmaxf(s[ni][2], s[ni][3]));
        }
        rm0 = fmaxf(rm0, __shfl_xor_sync(0xffffffffu, rm0, 1));
        rm0 = fmaxf(rm0, __shfl_xor_sync(0xffffffffu, rm0, 2));
        rm1 = fmaxf(rm1, __shfl_xor_sync(0xffffffffu, rm1, 1));
        rm1 = fmaxf(rm1, __shfl_xor_sync(0xffffffffu, rm1, 2));

        const float mn0 = fmaxf(m0r, rm0);
        const float mn1 = fmaxf(m1r, rm1);
        const float al0 = fexp2(m0r - mn0);
        const float al1 = fexp2(m1r - mn1);
        m0r = mn0; m1r = mn1;

        unsigned* Pw  = sm + APS + (wm + gid) * 68;
        unsigned* Pw8 = sm + APS + (wm + gid + 8) * 68;
        float ps0 = 0.0f, ps1 = 0.0f;
#pragma unroll
        for (int ni = 0; ni < 8; ++ni) {
            s[ni][0] = fexp2(s[ni][0] - mn0);
            s[ni][1] = fexp2(s[ni][1] - mn0);
            s[ni][2] = fexp2(s[ni][2] - mn1);
            s[ni][3] = fexp2(s[ni][3] - mn1);
            ps0 += s[ni][0] + s[ni][1];
            ps1 += s[ni][2] + s[ni][3];
            *(uint2*)(Pw + ni * 8 + 2 * tig)  = make_uint2(f2tf(s[ni][0]), f2tf(s[ni][1]));
            *(uint2*)(Pw8 + ni * 8 + 2 * tig) = make_uint2(f2tf(s[ni][2]), f2tf(s[ni][3]));
        }
        ps0 += __shfl_xor_sync(0xffffffffu, ps0, 1);
        ps0 += __shfl_xor_sync(0xffffffffu, ps0, 2);
        ps1 += __shfl_xor_sync(0xffffffffu, ps1, 1);
        ps1 += __shfl_xor_sync(0xffffffffu, ps1, 2);
        l0 = l0 * al0 + ps0;
        l1 = l1 * al1 + ps1;

#pragma unroll
        for (int ni = 0; ni < 8; ++ni) {
            O[ni][0] *= al0; O[ni][1] *= al0;
            O[ni][2] *= al1; O[ni][3] *= al1;
        }
        __syncwarp();

        // ---- O += P @ V ----
#pragma unroll
        for (int ks = 0; ks < 8; ++ks) {
            const int kk = ks * 8;
            const unsigned a0 = Pw[kk + tig];
            const unsigned a1 = Pw8[kk + tig];
            const unsigned a2 = Pw[kk + tig + 4];
            const unsigned a3 = Pw8[kk + tig + 4];
#pragma unroll
            for (int ni = 0; ni < 8; ++ni) {
                const unsigned b0 = Vst[(ni * 8 + gid) * 68 + kk + tig];
                const unsigned b1 = Vst[(ni * 8 + gid) * 68 + kk + tig + 4];
                mma_tf32(O[ni], a0, a1, a2, a3, b0, b1);
            }
        }

        // ---- store prefetched tile into the other buffer ----
        if (kt + 1 < NT) {
            const int nb = buf ^ 1;
            if (sel < 2) {
                unsigned* dst = sm + AKS + nb * 64 * 68 + kr * 68 + kdh;
#pragma unroll
                for (int u = 0; u < 8; ++u) *(uint4*)(dst + u * 4) = f2tf4(pf[u]);
            } else {
#pragma unroll
                for (int u = 0; u < 8; ++u) {
                    unsigned* dc = sm + AVT + nb * 64 * 68 + (kdh + u * 4) * 68 + kr;
                    dc[0]       = f2tf(pf[u].x);
                    dc[68]      = f2tf(pf[u].y);
                    dc[2 * 68]  = f2tf(pf[u].z);
                    dc[3 * 68]  = f2tf(pf[u].w);
                }
            }
            __syncthreads();
        }
    }

    // ---- normalize and write ctx[b, q, h, d] ----
    const float inv0 = 1.0f / l0;
    const float inv1 = 1.0f / l1;
    float* dst0 = g_ctx + (size_t)(b * NN + q0 + wm + gid) * EMBED + h * HDIM;
    float* dst1 = g_ctx + (size_t)(b * NN + q0 + wm + gid + 8) * EMBED + h * HDIM;
#pragma unroll
    for (int ni = 0; ni < 8; ++ni) {
        const int col = ni * 8 + 2 * tig;
        *(float2*)(dst0 + col) = make_float2(O[ni][0] * inv0, O[ni][1] * inv0);
        *(float2*)(dst1 + col) = make_float2(O[ni][2] * inv1, O[ni][3] * inv1);
    }
}

// ---------------------------------------------------------------------------
extern "C" void kernel_launch(void* const* d_in, const int* in_sizes, int n_in,
                              void* d_out, int out_size)
{
    (void)in_sizes; (void)n_in; (void)out_size;
    const float* x     = (const float*)d_in[0];
    const float* w_qkv = (const float*)d_in[1];
    const float* b_qkv = (const float*)d_in[2];
    const float* w_out = (const float*)d_in[3];
    const float* b_out = (const float*)d_in[4];
    float* out = (float*)d_out;

    float* qkv_p; float* ctx_p;
    cudaGetSymbolAddress((void**)&qkv_p, g_qkv);
    cudaGetSymbolAddress((void**)&ctx_p, g_ctx);

    static int attrs_set = 0;
    const int gemm_smem = 4 * GST * (int)sizeof(unsigned);        // 73728
    const int attn_smem = 512 * 68 * (int)sizeof(unsigned);       // 139264
    if (!attrs_set) {
        cudaFuncSetAttribute(gemm_tf32_db,
                             cudaFuncAttributeMaxDynamicSharedMemorySize, gemm_smem);
        cudaFuncSetAttribute(attn_flash_tf32_v2,
                             cudaFuncAttributeMaxDynamicSharedMemorySize, attn_smem);
        attrs_set = 1;
    }

    // 1) QKV projection: [8192,768] x [2304,768]^T
    {
        dim3 grid(QKVW / 128, MTOT / 128);
        gemm_tf32_db<<<grid, 256, gemm_smem>>>(x, w_qkv, b_qkv, qkv_p, MTOT, QKVW, EMBED);
    }

    // 2) Flash attention (tf32 mma, Q-tile 128, double-buffered K/V)
    {
        dim3 grid(NN / 128, BB * NHEAD);
        attn_flash_tf32_v2<<<grid, 256, attn_smem>>>();
    }

    // 3) Output projection: [8192,768] x [768,768]^T
    {
        dim3 grid(EMBED / 128, MTOT / 128);
        gemm_tf32_db<<<grid, 256, gemm_smem>>>(ctx_p, w_out, b_out, out, MTOT, EMBED, EMBED);
    }
}

// round 5
// speedup vs baseline: 2.8130x; 1.1990x over previous
#include <cuda_runtime.h>
#include <math.h>

#define EMBED 768
#define NHEAD 12
#define HDIM  64
#define BB    4
#define NN    2048
#define MTOT  (BB * NN)          // 8192
#define QKVW  (3 * EMBED)        // 2304

// Scratch (allocation-free rule: __device__ globals)
__device__ float g_qkv[(size_t)MTOT * QKVW];   // [B*N, 3*768] : Q|K|V per row
__device__ float g_ctx[(size_t)MTOT * EMBED];  // attention output, [b,n,h,d] packed

// ---------------------------------------------------------------------------
// helpers
// ---------------------------------------------------------------------------
__device__ __forceinline__ unsigned f2tf(float f) {
    unsigned u;
    asm("cvt.rna.tf32.f32 %0, %1;" : "=r"(u) : "f"(f));
    return u;
}
__device__ __forceinline__ uint4 f2tf4(float4 v) {
    uint4 r;
    r.x = f2tf(v.x); r.y = f2tf(v.y); r.z = f2tf(v.z); r.w = f2tf(v.w);
    return r;
}
__device__ __forceinline__ float fexp2(float x) {
    float y;
    asm("ex2.approx.ftz.f32 %0, %1;" : "=f"(y) : "f"(x));
    return y;
}
__device__ __forceinline__ void mma_tf32(float c[4],
                                         unsigned a0, unsigned a1, unsigned a2, unsigned a3,
                                         unsigned b0, unsigned b1) {
    asm volatile(
        "mma.sync.aligned.m16n8k8.row.col.f32.tf32.tf32.f32 "
        "{%0,%1,%2,%3}, {%4,%5,%6,%7}, {%8,%9}, {%0,%1,%2,%3};"
        : "+f"(c[0]), "+f"(c[1]), "+f"(c[2]), "+f"(c[3])
        : "r"(a0), "r"(a1), "r"(a2), "r"(a3), "r"(b0), "r"(b1));
}
// ldmatrix x4 (pure 32-bit data mover; tf32 fragments)
__device__ __forceinline__ void ldsm4(unsigned r[4], unsigned addr) {
    asm volatile("ldmatrix.sync.aligned.m8n8.x4.shared.b16 {%0,%1,%2,%3}, [%4];"
                 : "=r"(r[0]), "=r"(r[1]), "=r"(r[2]), "=r"(r[3]) : "r"(addr));
}
__device__ __forceinline__ unsigned smem_u32(const void* p) {
    return (unsigned)__cvta_generic_to_shared(p);
}

// ---------------------------------------------------------------------------
// tf32 GEMM (NT), double-buffered, ldmatrix fragments.
// C = A[M][K] @ B[Nn][K]^T + bias. 128x128 tile, BK=16, 256 thr, warp 64x32.
// Smem stride 36 words. Dynamic smem: 4 * 128*36 * 4 = 73728 B.
// ---------------------------------------------------------------------------
#define GST (128 * 36)

__global__ __launch_bounds__(256, 2) void gemm_tf32_db(
    const float* __restrict__ A, const float* __restrict__ B,
    const float* __restrict__ bias, float* __restrict__ C,
    int M, int Nn, int K)
{
    extern __shared__ unsigned gs[];
    unsigned* Asm = gs;              // [2][128][36]
    unsigned* Bsm = gs + 2 * GST;    // [2][128][36]

    const int tid  = threadIdx.x;
    const int lane = tid & 31;
    const int warp = tid >> 5;
    const int gid  = lane >> 2;
    const int tig  = lane & 3;

    const int wm = (warp >> 2) * 64;   // 0 or 64
    const int wn = (warp & 3) * 32;    // 0,32,64,96

    const int n0 = blockIdx.x * 128;
    const int m0 = blockIdx.y * 128;

    const int lrow = tid >> 1;
    const int lk   = (tid & 1) * 8;

    // ldmatrix per-lane row/col offsets
    const int arow = (lane & 7) + ((lane >> 3) & 1) * 8;   // A/P pattern
    const int acol = (lane >> 4) * 4;
    const int brow = (lane & 7) + ((lane >> 4) & 1) * 8;   // B pattern
    const int bcol = ((lane >> 3) & 1) * 4;

    const unsigned aBase = smem_u32(Asm) + ((wm + arow) * 36 + acol) * 4;
    const unsigned bBase = smem_u32(Bsm) + ((wn + brow) * 36 + bcol) * 4;

    float acc[4][4][4];
#pragma unroll
    for (int mi = 0; mi < 4; ++mi)
#pragma unroll
        for (int ni = 0; ni < 4; ++ni)
#pragma unroll
            for (int r = 0; r < 4; ++r) acc[mi][ni][r] = 0.0f;

    const float* Arow = A + (size_t)(m0 + lrow) * K + lk;
    const float* Brow = B + (size_t)(n0 + lrow) * K + lk;
    const int nT = K / 16;

    {
        float4 a0v = *(const float4*)(Arow);
        float4 a1v = *(const float4*)(Arow + 4);
        float4 b0v = *(const float4*)(Brow);
        float4 b1v = *(const float4*)(Brow + 4);
        *(uint4*)(Asm + lrow * 36 + lk)     = f2tf4(a0v);
        *(uint4*)(Asm + lrow * 36 + lk + 4) = f2tf4(a1v);
        *(uint4*)(Bsm + lrow * 36 + lk)     = f2tf4(b0v);
        *(uint4*)(Bsm + lrow * 36 + lk + 4) = f2tf4(b1v);
    }
    __syncthreads();

    for (int kt = 0; kt < nT; ++kt) {
        const int st = kt & 1;
        float4 a0v, a1v, b0v, b1v;
        if (kt + 1 < nT) {
            const int ko = (kt + 1) * 16;
            a0v = *(const float4*)(Arow + ko);
            a1v = *(const float4*)(Arow + ko + 4);
            b0v = *(const float4*)(Brow + ko);
            b1v = *(const float4*)(Brow + ko + 4);
        }

        const unsigned aS = aBase + st * (GST * 4);
        const unsigned bS = bBase + st * (GST * 4);
#pragma unroll
        for (int ks = 0; ks < 2; ++ks) {
            const unsigned koff = ks * 32;   // 8 words
            unsigned af[4][4], bf[2][4];
#pragma unroll
            for (int mi = 0; mi < 4; ++mi)
                ldsm4(af[mi], aS + mi * (16 * 36 * 4) + koff);
#pragma unroll
            for (int p = 0; p < 2; ++p)
                ldsm4(bf[p], bS + p * (16 * 36 * 4) + koff);
#pragma unroll
            for (int mi = 0; mi < 4; ++mi)
#pragma unroll
                for (int ni = 0; ni < 4; ++ni)
                    mma_tf32(acc[mi][ni], af[mi][0], af[mi][1], af[mi][2], af[mi][3],
                             bf[ni >> 1][(ni & 1) * 2], bf[ni >> 1][(ni & 1) * 2 + 1]);
        }

        if (kt + 1 < nT) {
            unsigned* Ad = Asm + (st ^ 1) * GST;
            unsigned* Bd = Bsm + (st ^ 1) * GST;
            __syncthreads();
            *(uint4*)(Ad + lrow * 36 + lk)     = f2tf4(a0v);
            *(uint4*)(Ad + lrow * 36 + lk + 4) = f2tf4(a1v);
            *(uint4*)(Bd + lrow * 36 + lk)     = f2tf4(b0v);
            *(uint4*)(Bd + lrow * 36 + lk + 4) = f2tf4(b1v);
            __syncthreads();
        }
    }

#pragma unroll
    for (int ni = 0; ni < 4; ++ni) {
        const int col = n0 + wn + ni * 8 + 2 * tig;
        const float bx = bias[col];
        const float by = bias[col + 1];
#pragma unroll
        for (int mi = 0; mi < 4; ++mi) {
            const int row = m0 + wm + mi * 16 + gid;
            *(float2*)(C + (size_t)row * Nn + col) =
                make_float2(acc[mi][ni][0] + bx, acc[mi][ni][1] + by);
            *(float2*)(C + (size_t)(row + 8) * Nn + col) =
                make_float2(acc[mi][ni][2] + bx, acc[mi][ni][3] + by);
        }
    }
}

// ---------------------------------------------------------------------------
// Flash attention, tf32 MMA + ldmatrix, Q-tile 128 / K-tile 64, 256 threads,
// SINGLE-buffered K/V (2 CTAs/SM), register prefetch.
// Smem words: Qs[128][68] | Ks[64][68] | Vt[64][68] | Ps[128][68] = 104448 B.
// ---------------------------------------------------------------------------
#define AQS 0
#define AKS (128 * 68)
#define AVT (AKS + 64 * 68)
#define APS (AVT + 64 * 68)

__global__ __launch_bounds__(256, 2) void attn_flash_tf32_v3()
{
    extern __shared__ unsigned sm[];

    const int tid  = threadIdx.x;
    const int lane = tid & 31;
    const int warp = tid >> 5;
    const int gid  = lane >> 2;
    const int tig  = lane & 3;
    const int wm   = warp * 16;

    const int b  = blockIdx.y / NHEAD;
    const int h  = blockIdx.y % NHEAD;
    const int q0 = blockIdx.x * 128;

    // ldmatrix lane offsets
    const int arow = (lane & 7) + ((lane >> 3) & 1) * 8;
    const int acol = (lane >> 4) * 4;
    const int brow = (lane & 7) + ((lane >> 4) & 1) * 8;
    const int bcol = ((lane >> 3) & 1) * 4;

    const unsigned smBase = smem_u32(sm);
    const unsigned qA = smBase + (AQS + (wm + arow) * 68 + acol) * 4;
    const unsigned pA = smBase + (APS + (wm + arow) * 68 + acol) * 4;
    const unsigned kB = smBase + (AKS + brow * 68 + bcol) * 4;
    const unsigned vB = smBase + (AVT + brow * 68 + bcol) * 4;

    // ---- load Q tile (scaled into log2 domain) ----
    {
        const int qrow = tid & 127;
        const int qdh  = (tid >> 7) * 32;
        const float qs = 0.125f * 1.4426950408889634f;
        const float* src = g_qkv + (size_t)(b * NN + q0 + qrow) * QKVW + h * HDIM + qdh;
        unsigned* dst = sm + AQS + qrow * 68 + qdh;
#pragma unroll
        for (int u = 0; u < 8; ++u) {
            float4 v = *(const float4*)(src + u * 4);
            uint4 w;
            w.x = f2tf(v.x * qs); w.y = f2tf(v.y * qs);
            w.z = f2tf(v.z * qs); w.w = f2tf(v.w * qs);
            *(uint4*)(dst + u * 4) = w;
        }
    }

    // K/V loader mapping: kr = row in tile, sel 0,1 = K halves; 2,3 = V halves
    const int kr   = tid & 63;
    const int sel  = tid >> 6;
    const int kdh  = (sel & 1) * 32;
    const size_t kvoff = (size_t)h * HDIM + kdh + ((sel >> 1) ? 2 * EMBED : EMBED);

    float4 pf[8];
    // prologue: tile 0 -> smem, prefetch tile 1 -> regs
    {
        const float* srcp = g_qkv + (size_t)(b * NN + kr) * QKVW + kvoff;
#pragma unroll
        for (int u = 0; u < 8; ++u) pf[u] = *(const float4*)(srcp + u * 4);
        if (sel < 2) {
            unsigned* dst = sm + AKS + kr * 68 + kdh;
#pragma unroll
            for (int u = 0; u < 8; ++u) *(uint4*)(dst + u * 4) = f2tf4(pf[u]);
        } else {
#pragma unroll
            for (int u = 0; u < 8; ++u) {
                unsigned* dc = sm + AVT + (kdh + u * 4) * 68 + kr;
                dc[0] = f2tf(pf[u].x); dc[68] = f2tf(pf[u].y);
                dc[2 * 68] = f2tf(pf[u].z); dc[3 * 68] = f2tf(pf[u].w);
            }
        }
        const float* srcn = g_qkv + (size_t)(b * NN + 64 + kr) * QKVW + kvoff;
#pragma unroll
        for (int u = 0; u < 8; ++u) pf[u] = *(const float4*)(srcn + u * 4);
    }
    __syncthreads();

    float m0r = -1.0e30f, m1r = -1.0e30f;
    float l0 = 0.0f, l1 = 0.0f;
    float O[8][4];
#pragma unroll
    for (int ni = 0; ni < 8; ++ni)
#pragma unroll
        for (int r = 0; r < 4; ++r) O[ni][r] = 0.0f;

    const int NT = NN / 64;
    for (int kt = 0; kt < NT; ++kt) {
        // ---- S = Qhat @ K^T ----
        float s[8][4];
#pragma unroll
        for (int ni = 0; ni < 8; ++ni)
#pragma unroll
            for (int r = 0; r < 4; ++r) s[ni][r] = 0.0f;
#pragma unroll
        for (int ks = 0; ks < 8; ++ks) {
            const unsigned koff = ks * 32;
            unsigned aq[4], bk[4][4];
            ldsm4(aq, qA + koff);
#pragma unroll
            for (int p = 0; p < 4; ++p)
                ldsm4(bk[p], kB + p * (16 * 68 * 4) + koff);
#pragma unroll
            for (int ni = 0; ni < 8; ++ni)
                mma_tf32(s[ni], aq[0], aq[1], aq[2], aq[3],
                         bk[ni >> 1][(ni & 1) * 2], bk[ni >> 1][(ni & 1) * 2 + 1]);
        }

        // ---- online softmax (log2 domain) ----
        float rm0 = -1.0e30f, rm1 = -1.0e30f;
#pragma unroll
        for (int ni = 0; ni < 8; ++ni) {
            rm0 = fmaxf(rm0, fmaxf(s[ni][0], s[ni][1]));
            rm1 = fmaxf(rm1, fmaxf(s[ni][2], s[ni][3]));
        }
        rm0 = fmaxf(rm0, __shfl_xor_sync(0xffffffffu, rm0, 1));
        rm0 = fmaxf(rm0, __shfl_xor_sync(0xffffffffu, rm0, 2));
        rm1 = fmaxf(rm1, __shfl_xor_sync(0xffffffffu, rm1, 1));
        rm1 = fmaxf(rm1, __shfl_xor_sync(0xffffffffu, rm1, 2));

        const float mn0 = fmaxf(m0r, rm0);
        const float mn1 = fmaxf(m1r, rm1);
        const float al0 = fexp2(m0r - mn0);
        const float al1 = fexp2(m1r - mn1);
        m0r = mn0; m1r = mn1;

        unsigned* Pw  = sm + APS + (wm + gid) * 68;
        unsigned* Pw8 = sm + APS + (wm + gid + 8) * 68;
        float ps0 = 0.0f, ps1 = 0.0f;
#pragma unroll
        for (int ni = 0; ni < 8; ++ni) {
            s[ni][0] = fexp2(s[ni][0] - mn0);
            s[ni][1] = fexp2(s[ni][1] - mn0);
            s[ni][2] = fexp2(s[ni][2] - mn1);
            s[ni][3] = fexp2(s[ni][3] - mn1);
            ps0 += s[ni][0] + s[ni][1];
            ps1 += s[ni][2] + s[ni][3];
            *(uint2*)(Pw + ni * 8 + 2 * tig)  = make_uint2(f2tf(s[ni][0]), f2tf(s[ni][1]));
            *(uint2*)(Pw8 + ni * 8 + 2 * tig) = make_uint2(f2tf(s[ni][2]), f2tf(s[ni][3]));
        }
        ps0 += __shfl_xor_sync(0xffffffffu, ps0, 1);
        ps0 += __shfl_xor_sync(0xffffffffu, ps0, 2);
        ps1 += __shfl_xor_sync(0xffffffffu, ps1, 1);
        ps1 += __shfl_xor_sync(0xffffffffu, ps1, 2);
        l0 = l0 * al0 + ps0;
        l1 = l1 * al1 + ps1;

#pragma unroll
        for (int ni = 0; ni < 8; ++ni) {
            O[ni][0] *= al0; O[ni][1] *= al0;
            O[ni][2] *= al1; O[ni][3] *= al1;
        }
        __syncwarp();

        // ---- O += P @ V ----
#pragma unroll
        for (int ks = 0; ks < 8; ++ks) {
            const unsigned koff = ks * 32;
            unsigned ap[4], bv[4][4];
            ldsm4(ap, pA + koff);
#pragma unroll
            for (int p = 0; p < 4; ++p)
                ldsm4(bv[p], vB + p * (16 * 68 * 4) + koff);
#pragma unroll
            for (int ni = 0; ni < 8; ++ni)
                mma_tf32(O[ni], ap[0], ap[1], ap[2], ap[3],
                         bv[ni >> 1][(ni & 1) * 2], bv[ni >> 1][(ni & 1) * 2 + 1]);
        }

        // ---- rotate: store prefetched tile, prefetch next ----
        if (kt + 1 < NT) {
            __syncthreads();   // all warps done reading current K/V
            if (sel < 2) {
                unsigned* dst = sm + AKS + kr * 68 + kdh;
#pragma unroll
                for (int u = 0; u < 8; ++u) *(uint4*)(dst + u * 4) = f2tf4(pf[u]);
            } else {
#pragma unroll
                for (int u = 0; u < 8; ++u) {
                    unsigned* dc = sm + AVT + (kdh + u * 4) * 68 + kr;
                    dc[0] = f2tf(pf[u].x); dc[68] = f2tf(pf[u].y);
                    dc[2 * 68] = f2tf(pf[u].z); dc[3 * 68] = f2tf(pf[u].w);
                }
            }
            if (kt + 2 < NT) {
                const float* srcn = g_qkv + (size_t)(b * NN + (kt + 2) * 64 + kr) * QKVW + kvoff;
#pragma unroll
                for (int u = 0; u < 8; ++u) pf[u] = *(const float4*)(srcn + u * 4);
            }
            __syncthreads();
        }
    }

    // ---- normalize and write ctx[b, q, h, d] ----
    const float inv0 = 1.0f / l0;
    const float inv1 = 1.0f / l1;
    float* dst0 = g_ctx + (size_t)(b * NN + q0 + wm + gid) * EMBED + h * HDIM;
    float* dst1 = g_ctx + (size_t)(b * NN + q0 + wm + gid + 8) * EMBED + h * HDIM;
#pragma unroll
    for (int ni = 0; ni < 8; ++ni) {
        const int col = ni * 8 + 2 * tig;
        *(float2*)(dst0 + col) = make_float2(O[ni][0] * inv0, O[ni][1] * inv0);
        *(float2*)(dst1 + col) = make_float2(O[ni][2] * inv1, O[ni][3] * inv1);
    }
}

// ---------------------------------------------------------------------------
extern "C" void kernel_launch(void* const* d_in, const int* in_sizes, int n_in,
                              void* d_out, int out_size)
{
    (void)in_sizes; (void)n_in; (void)out_size;
    const float* x     = (const float*)d_in[0];
    const float* w_qkv = (const float*)d_in[1];
    const float* b_qkv = (const float*)d_in[2];
    const float* w_out = (const float*)d_in[3];
    const float* b_out = (const float*)d_in[4];
    float* out = (float*)d_out;

    float* qkv_p; float* ctx_p;
    cudaGetSymbolAddress((void**)&qkv_p, g_qkv);
    cudaGetSymbolAddress((void**)&ctx_p, g_ctx);

    static int attrs_set = 0;
    const int gemm_smem = 4 * GST * (int)sizeof(unsigned);        // 73728
    const int attn_smem = 384 * 68 * (int)sizeof(unsigned);       // 104448
    if (!attrs_set) {
        cudaFuncSetAttribute(gemm_tf32_db,
                             cudaFuncAttributeMaxDynamicSharedMemorySize, gemm_smem);
        cudaFuncSetAttribute(attn_flash_tf32_v3,
                             cudaFuncAttributeMaxDynamicSharedMemorySize, attn_smem);
        attrs_set = 1;
    }

    {
        dim3 grid(QKVW / 128, MTOT / 128);
        gemm_tf32_db<<<grid, 256, gemm_smem>>>(x, w_qkv, b_qkv, qkv_p, MTOT, QKVW, EMBED);
    }
    {
        dim3 grid(NN / 128, BB * NHEAD);
        attn_flash_tf32_v3<<<grid, 256, attn_smem>>>();
    }
    {
        dim3 grid(EMBED / 128, MTOT / 128);
        gemm_tf32_db<<<grid, 256, gemm_smem>>>(ctx_p, w_out, b_out, out, MTOT, EMBED, EMBED);
    }
}

// round 6
// speedup vs baseline: 3.3322x; 1.1846x over previous
#include <cuda_runtime.h>
#include <cuda_fp16.h>
#include <math.h>

#define EMBED 768
#define NHEAD 12
#define HDIM  64
#define BB    4
#define NN    2048
#define MTOT  (BB * NN)          // 8192
#define QKVW  (3 * EMBED)        // 2304

// Scratch (allocation-free rule: __device__ globals)
__device__ float g_qkv[(size_t)MTOT * QKVW];   // [B*N, 3*768] : Q|K|V per row
__device__ float g_ctx[(size_t)MTOT * EMBED];  // attention output, [b,n,h,d] packed

// ---------------------------------------------------------------------------
// helpers
// ---------------------------------------------------------------------------
__device__ __forceinline__ unsigned f2tf(float f) {
    unsigned u;
    asm("cvt.rna.tf32.f32 %0, %1;" : "=r"(u) : "f"(f));
    return u;
}
__device__ __forceinline__ uint4 f2tf4(float4 v) {
    uint4 r;
    r.x = f2tf(v.x); r.y = f2tf(v.y); r.z = f2tf(v.z); r.w = f2tf(v.w);
    return r;
}
__device__ __forceinline__ float fexp2(float x) {
    float y;
    asm("ex2.approx.ftz.f32 %0, %1;" : "=f"(y) : "f"(x));
    return y;
}
__device__ __forceinline__ void mma_tf32(float c[4],
                                         unsigned a0, unsigned a1, unsigned a2, unsigned a3,
                                         unsigned b0, unsigned b1) {
    asm volatile(
        "mma.sync.aligned.m16n8k8.row.col.f32.tf32.tf32.f32 "
        "{%0,%1,%2,%3}, {%4,%5,%6,%7}, {%8,%9}, {%0,%1,%2,%3};"
        : "+f"(c[0]), "+f"(c[1]), "+f"(c[2]), "+f"(c[3])
        : "r"(a0), "r"(a1), "r"(a2), "r"(a3), "r"(b0), "r"(b1));
}
__device__ __forceinline__ void mma_f16(float c[4],
                                        unsigned a0, unsigned a1, unsigned a2, unsigned a3,
                                        unsigned b0, unsigned b1) {
    asm volatile(
        "mma.sync.aligned.m16n8k16.row.col.f32.f16.f16.f32 "
        "{%0,%1,%2,%3}, {%4,%5,%6,%7}, {%8,%9}, {%0,%1,%2,%3};"
        : "+f"(c[0]), "+f"(c[1]), "+f"(c[2]), "+f"(c[3])
        : "r"(a0), "r"(a1), "r"(a2), "r"(a3), "r"(b0), "r"(b1));
}
__device__ __forceinline__ void ldsm4(unsigned r[4], unsigned addr) {
    asm volatile("ldmatrix.sync.aligned.m8n8.x4.shared.b16 {%0,%1,%2,%3}, [%4];"
                 : "=r"(r[0]), "=r"(r[1]), "=r"(r[2]), "=r"(r[3]) : "r"(addr));
}
__device__ __forceinline__ unsigned smem_u32(const void* p) {
    return (unsigned)__cvta_generic_to_shared(p);
}
__device__ __forceinline__ unsigned pack_h2(float lo, float hi) {
    __half2 h = __floats2half2_rn(lo, hi);
    return *reinterpret_cast<unsigned*>(&h);
}

// ---------------------------------------------------------------------------
// tf32 GEMM (NT), double-buffered, ldmatrix fragments.  (unchanged from R4)
// ---------------------------------------------------------------------------
#define GST (128 * 36)

__global__ __launch_bounds__(256, 2) void gemm_tf32_db(
    const float* __restrict__ A, const float* __restrict__ B,
    const float* __restrict__ bias, float* __restrict__ C,
    int M, int Nn, int K)
{
    extern __shared__ unsigned gs[];
    unsigned* Asm = gs;              // [2][128][36]
    unsigned* Bsm = gs + 2 * GST;    // [2][128][36]

    const int tid  = threadIdx.x;
    const int lane = tid & 31;
    const int warp = tid >> 5;
    const int gid  = lane >> 2;
    const int tig  = lane & 3;

    const int wm = (warp >> 2) * 64;
    const int wn = (warp & 3) * 32;

    const int n0 = blockIdx.x * 128;
    const int m0 = blockIdx.y * 128;

    const int lrow = tid >> 1;
    const int lk   = (tid & 1) * 8;

    const int arow = (lane & 7) + ((lane >> 3) & 1) * 8;
    const int acol = (lane >> 4) * 4;
    const int brow = (lane & 7) + ((lane >> 4) & 1) * 8;
    const int bcol = ((lane >> 3) & 1) * 4;

    const unsigned aBase = smem_u32(Asm) + ((wm + arow) * 36 + acol) * 4;
    const unsigned bBase = smem_u32(Bsm) + ((wn + brow) * 36 + bcol) * 4;

    float acc[4][4][4];
#pragma unroll
    for (int mi = 0; mi < 4; ++mi)
#pragma unroll
        for (int ni = 0; ni < 4; ++ni)
#pragma unroll
            for (int r = 0; r < 4; ++r) acc[mi][ni][r] = 0.0f;

    const float* Arow = A + (size_t)(m0 + lrow) * K + lk;
    const float* Brow = B + (size_t)(n0 + lrow) * K + lk;
    const int nT = K / 16;

    {
        float4 a0v = *(const float4*)(Arow);
        float4 a1v = *(const float4*)(Arow + 4);
        float4 b0v = *(const float4*)(Brow);
        float4 b1v = *(const float4*)(Brow + 4);
        *(uint4*)(Asm + lrow * 36 + lk)     = f2tf4(a0v);
        *(uint4*)(Asm + lrow * 36 + lk + 4) = f2tf4(a1v);
        *(uint4*)(Bsm + lrow * 36 + lk)     = f2tf4(b0v);
        *(uint4*)(Bsm + lrow * 36 + lk + 4) = f2tf4(b1v);
    }
    __syncthreads();

    for (int kt = 0; kt < nT; ++kt) {
        const int st = kt & 1;
        float4 a0v, a1v, b0v, b1v;
        if (kt + 1 < nT) {
            const int ko = (kt + 1) * 16;
            a0v = *(const float4*)(Arow + ko);
            a1v = *(const float4*)(Arow + ko + 4);
            b0v = *(const float4*)(Brow + ko);
            b1v = *(const float4*)(Brow + ko + 4);
        }

        const unsigned aS = aBase + st * (GST * 4);
        const unsigned bS = bBase + st * (GST * 4);
#pragma unroll
        for (int ks = 0; ks < 2; ++ks) {
            const unsigned koff = ks * 32;
            unsigned af[4][4], bf[2][4];
#pragma unroll
            for (int mi = 0; mi < 4; ++mi)
                ldsm4(af[mi], aS + mi * (16 * 36 * 4) + koff);
#pragma unroll
            for (int p = 0; p < 2; ++p)
                ldsm4(bf[p], bS + p * (16 * 36 * 4) + koff);
#pragma unroll
            for (int mi = 0; mi < 4; ++mi)
#pragma unroll
                for (int ni = 0; ni < 4; ++ni)
                    mma_tf32(acc[mi][ni], af[mi][0], af[mi][1], af[mi][2], af[mi][3],
                             bf[ni >> 1][(ni & 1) * 2], bf[ni >> 1][(ni & 1) * 2 + 1]);
        }

        if (kt + 1 < nT) {
            unsigned* Ad = Asm + (st ^ 1) * GST;
            unsigned* Bd = Bsm + (st ^ 1) * GST;
            __syncthreads();
            *(uint4*)(Ad + lrow * 36 + lk)     = f2tf4(a0v);
            *(uint4*)(Ad + lrow * 36 + lk + 4) = f2tf4(a1v);
            *(uint4*)(Bd + lrow * 36 + lk)     = f2tf4(b0v);
            *(uint4*)(Bd + lrow * 36 + lk + 4) = f2tf4(b1v);
            __syncthreads();
        }
    }

#pragma unroll
    for (int ni = 0; ni < 4; ++ni) {
        const int col = n0 + wn + ni * 8 + 2 * tig;
        const float bx = bias[col];
        const float by = bias[col + 1];
#pragma unroll
        for (int mi = 0; mi < 4; ++mi) {
            const int row = m0 + wm + mi * 16 + gid;
            *(float2*)(C + (size_t)row * Nn + col) =
                make_float2(acc[mi][ni][0] + bx, acc[mi][ni][1] + by);
            *(float2*)(C + (size_t)(row + 8) * Nn + col) =
                make_float2(acc[mi][ni][2] + bx, acc[mi][ni][3] + by);
        }
    }
}

// ---------------------------------------------------------------------------
// Flash attention v4: QK^T in tf32 mma; P kept in registers as fp16
// m16n8k16 A-fragments (NO smem round-trip); V stored fp16 transposed.
// Q-tile 128 / K-tile 64, 256 threads, single-buffered K/V + reg prefetch.
// Smem: Qs[128][68] u32 | Ks[64][68] u32 | Vt[64][72] half = 61440 B.
// ---------------------------------------------------------------------------
#define AQS 0
#define AKS (128 * 68)
#define AVTW (AKS + 64 * 68)           // word offset of Vt (half array)
#define ATT_SMEM_BYTES (AVTW * 4 + 64 * 72 * 2)   // 61440

__global__ __launch_bounds__(256, 2) void attn_flash_tf32_v4()
{
    extern __shared__ unsigned sm[];
    __half* vt = (__half*)(sm + AVTW);

    const int tid  = threadIdx.x;
    const int lane = tid & 31;
    const int warp = tid >> 5;
    const int gid  = lane >> 2;
    const int tig  = lane & 3;
    const int wm   = warp * 16;

    const int b  = blockIdx.y / NHEAD;
    const int h  = blockIdx.y % NHEAD;
    const int q0 = blockIdx.x * 128;

    // ldmatrix lane offsets (tf32 A/B patterns)
    const int arow = (lane & 7) + ((lane >> 3) & 1) * 8;
    const int acol = (lane >> 4) * 4;
    const int brow = (lane & 7) + ((lane >> 4) & 1) * 8;
    const int bcol = ((lane >> 3) & 1) * 4;

    const unsigned smBase = smem_u32(sm);
    const unsigned qA = smBase + (AQS + (wm + arow) * 68 + acol) * 4;
    const unsigned kB = smBase + (AKS + brow * 68 + bcol) * 4;

    // V (half) ldmatrix address: mats cover (d 16p+{0..7}/{8..15}, keys 16j+{0..7}/{8..15})
    const int vrow = (lane & 7) + ((lane >> 4) & 1) * 8;   // d within 16-group
    const int vkey = ((lane >> 3) & 1) * 8;                // key offset within 16
    const unsigned vBbase = smem_u32(vt) + (vrow * 72 + vkey) * 2;

    // ---- load Q tile (scaled into log2 domain) ----
    {
        const int qrow = tid & 127;
        const int qdh  = (tid >> 7) * 32;
        const float qs = 0.125f * 1.4426950408889634f;
        const float* src = g_qkv + (size_t)(b * NN + q0 + qrow) * QKVW + h * HDIM + qdh;
        unsigned* dst = sm + AQS + qrow * 68 + qdh;
#pragma unroll
        for (int u = 0; u < 8; ++u) {
            float4 v = *(const float4*)(src + u * 4);
            uint4 w;
            w.x = f2tf(v.x * qs); w.y = f2tf(v.y * qs);
            w.z = f2tf(v.z * qs); w.w = f2tf(v.w * qs);
            *(uint4*)(dst + u * 4) = w;
        }
    }

    // K/V loader mapping: kr = row in tile, sel 0,1 = K halves; 2,3 = V halves
    const int kr   = tid & 63;
    const int sel  = tid >> 6;
    const int kdh  = (sel & 1) * 32;
    const size_t kvoff = (size_t)h * HDIM + kdh + ((sel >> 1) ? 2 * EMBED : EMBED);

    float4 pf[8];
    // prologue: tile 0 -> smem, prefetch tile 1 -> regs
    {
        const float* srcp = g_qkv + (size_t)(b * NN + kr) * QKVW + kvoff;
#pragma unroll
        for (int u = 0; u < 8; ++u) pf[u] = *(const float4*)(srcp + u * 4);
        if (sel < 2) {
            unsigned* dst = sm + AKS + kr * 68 + kdh;
#pragma unroll
            for (int u = 0; u < 8; ++u) *(uint4*)(dst + u * 4) = f2tf4(pf[u]);
        } else {
#pragma unroll
            for (int u = 0; u < 8; ++u) {
                __half* dc = vt + (kdh + u * 4) * 72 + kr;
                dc[0]      = __float2half(pf[u].x);
                dc[72]     = __float2half(pf[u].y);
                dc[144]    = __float2half(pf[u].z);
                dc[216]    = __float2half(pf[u].w);
            }
        }
        const float* srcn = g_qkv + (size_t)(b * NN + 64 + kr) * QKVW + kvoff;
#pragma unroll
        for (int u = 0; u < 8; ++u) pf[u] = *(const float4*)(srcn + u * 4);
    }
    __syncthreads();

    float m0r = -1.0e30f, m1r = -1.0e30f;
    float l0 = 0.0f, l1 = 0.0f;
    float O[8][4];
#pragma unroll
    for (int ni = 0; ni < 8; ++ni)
#pragma unroll
        for (int r = 0; r < 4; ++r) O[ni][r] = 0.0f;

    const int NT = NN / 64;
    for (int kt = 0; kt < NT; ++kt) {
        // ---- S = Qhat @ K^T (tf32) ----
        float s[8][4];
#pragma unroll
        for (int ni = 0; ni < 8; ++ni)
#pragma unroll
            for (int r = 0; r < 4; ++r) s[ni][r] = 0.0f;
#pragma unroll
        for (int ks = 0; ks < 8; ++ks) {
            const unsigned koff = ks * 32;
            unsigned aq[4], bk[4][4];
            ldsm4(aq, qA + koff);
#pragma unroll
            for (int p = 0; p < 4; ++p)
                ldsm4(bk[p], kB + p * (16 * 68 * 4) + koff);
#pragma unroll
            for (int ni = 0; ni < 8; ++ni)
                mma_tf32(s[ni], aq[0], aq[1], aq[2], aq[3],
                         bk[ni >> 1][(ni & 1) * 2], bk[ni >> 1][(ni & 1) * 2 + 1]);
        }

        // ---- online softmax (log2 domain) ----
        float rm0 = -1.0e30f, rm1 = -1.0e30f;
#pragma unroll
        for (int ni = 0; ni < 8; ++ni) {
            rm0 = fmaxf(rm0, fmaxf(s[ni][0], s[ni][1]));
            rm1 = fmaxf(rm1, fmaxf(s[ni][2], s[ni][3]));
        }
        rm0 = fmaxf(rm0, __shfl_xor_sync(0xffffffffu, rm0, 1));
        rm0 = fmaxf(rm0, __shfl_xor_sync(0xffffffffu, rm0, 2));
        rm1 = fmaxf(rm1, __shfl_xor_sync(0xffffffffu, rm1, 1));
        rm1 = fmaxf(rm1, __shfl_xor_sync(0xffffffffu, rm1, 2));

        const float mn0 = fmaxf(m0r, rm0);
        const float mn1 = fmaxf(m1r, rm1);
        const float al0 = fexp2(m0r - mn0);
        const float al1 = fexp2(m1r - mn1);
        m0r = mn0; m1r = mn1;

        float ps0 = 0.0f, ps1 = 0.0f;
#pragma unroll
        for (int ni = 0; ni < 8; ++ni) {
            s[ni][0] = fexp2(s[ni][0] - mn0);
            s[ni][1] = fexp2(s[ni][1] - mn0);
            s[ni][2] = fexp2(s[ni][2] - mn1);
            s[ni][3] = fexp2(s[ni][3] - mn1);
            ps0 += s[ni][0] + s[ni][1];
            ps1 += s[ni][2] + s[ni][3];
        }
        ps0 += __shfl_xor_sync(0xffffffffu, ps0, 1);
        ps0 += __shfl_xor_sync(0xffffffffu, ps0, 2);
        ps1 += __shfl_xor_sync(0xffffffffu, ps1, 1);
        ps1 += __shfl_xor_sync(0xffffffffu, ps1, 2);
        l0 = l0 * al0 + ps0;
        l1 = l1 * al1 + ps1;

#pragma unroll
        for (int ni = 0; ni < 8; ++ni) {
            O[ni][0] *= al0; O[ni][1] *= al0;
            O[ni][2] *= al1; O[ni][3] *= al1;
        }

        // ---- O += P @ V : P stays in registers as fp16 A-fragments ----
#pragma unroll
        for (int j = 0; j < 4; ++j) {
            const unsigned a0 = pack_h2(s[2 * j][0],     s[2 * j][1]);
            const unsigned a1 = pack_h2(s[2 * j][2],     s[2 * j][3]);
            const unsigned a2 = pack_h2(s[2 * j + 1][0], s[2 * j + 1][1]);
            const unsigned a3 = pack_h2(s[2 * j + 1][2], s[2 * j + 1][3]);
#pragma unroll
            for (int p = 0; p < 4; ++p) {
                unsigned bv[4];
                ldsm4(bv, vBbase + p * (16 * 72 * 2) + j * 32);
                mma_f16(O[2 * p],     a0, a1, a2, a3, bv[0], bv[1]);
                mma_f16(O[2 * p + 1], a0, a1, a2, a3, bv[2], bv[3]);
            }
        }

        // ---- rotate: store prefetched tile, prefetch next ----
        if (kt + 1 < NT) {
            __syncthreads();   // all warps done reading current K/V
            if (sel < 2) {
                unsigned* dst = sm + AKS + kr * 68 + kdh;
#pragma unroll
                for (int u = 0; u < 8; ++u) *(uint4*)(dst + u * 4) = f2tf4(pf[u]);
            } else {
#pragma unroll
                for (int u = 0; u < 8; ++u) {
                    __half* dc = vt + (kdh + u * 4) * 72 + kr;
                    dc[0]   = __float2half(pf[u].x);
                    dc[72]  = __float2half(pf[u].y);
                    dc[144] = __float2half(pf[u].z);
                    dc[216] = __float2half(pf[u].w);
                }
            }
            if (kt + 2 < NT) {
                const float* srcn = g_qkv + (size_t)(b * NN + (kt + 2) * 64 + kr) * QKVW + kvoff;
#pragma unroll
                for (int u = 0; u < 8; ++u) pf[u] = *(const float4*)(srcn + u * 4);
            }
            __syncthreads();
        }
    }

    // ---- normalize and write ctx[b, q, h, d] ----
    const float inv0 = 1.0f / l0;
    const float inv1 = 1.0f / l1;
    float* dst0 = g_ctx + (size_t)(b * NN + q0 + wm + gid) * EMBED + h * HDIM;
    float* dst1 = g_ctx + (size_t)(b * NN + q0 + wm + gid + 8) * EMBED + h * HDIM;
#pragma unroll
    for (int ni = 0; ni < 8; ++ni) {
        const int col = ni * 8 + 2 * tig;
        *(float2*)(dst0 + col) = make_float2(O[ni][0] * inv0, O[ni][1] * inv0);
        *(float2*)(dst1 + col) = make_float2(O[ni][2] * inv1, O[ni][3] * inv1);
    }
}

// ---------------------------------------------------------------------------
extern "C" void kernel_launch(void* const* d_in, const int* in_sizes, int n_in,
                              void* d_out, int out_size)
{
    (void)in_sizes; (void)n_in; (void)out_size;
    const float* x     = (const float*)d_in[0];
    const float* w_qkv = (const float*)d_in[1];
    const float* b_qkv = (const float*)d_in[2];
    const float* w_out = (const float*)d_in[3];
    const float* b_out = (const float*)d_in[4];
    float* out = (float*)d_out;

    float* qkv_p; float* ctx_p;
    cudaGetSymbolAddress((void**)&qkv_p, g_qkv);
    cudaGetSymbolAddress((void**)&ctx_p, g_ctx);

    static int attrs_set = 0;
    const int gemm_smem = 4 * GST * (int)sizeof(unsigned);        // 73728
    const int attn_smem = ATT_SMEM_BYTES;                          // 61440
    if (!attrs_set) {
        cudaFuncSetAttribute(gemm_tf32_db,
                             cudaFuncAttributeMaxDynamicSharedMemorySize, gemm_smem);
        cudaFuncSetAttribute(attn_flash_tf32_v4,
                             cudaFuncAttributeMaxDynamicSharedMemorySize, attn_smem);
        attrs_set = 1;
    }

    {
        dim3 grid(QKVW / 128, MTOT / 128);
        gemm_tf32_db<<<grid, 256, gemm_smem>>>(x, w_qkv, b_qkv, qkv_p, MTOT, QKVW, EMBED);
    }
    {
        dim3 grid(NN / 128, BB * NHEAD);
        attn_flash_tf32_v4<<<grid, 256, attn_smem>>>();
    }
    {
        dim3 grid(EMBED / 128, MTOT / 128);
        gemm_tf32_db<<<grid, 256, gemm_smem>>>(ctx_p, w_out, b_out, out, MTOT, EMBED, EMBED);
    }
}

// round 8
// speedup vs baseline: 4.3214x; 1.2969x over previous
#include <cuda_runtime.h>
#include <cuda_fp16.h>
#include <math.h>

#define EMBED 768
#define NHEAD 12
#define HDIM  64
#define BB    4
#define NN    2048
#define MTOT  (BB * NN)          // 8192
#define QKVW  (3 * EMBED)        // 2304

// Scratch (allocation-free rule: __device__ globals)
__device__ float g_qkv[(size_t)MTOT * QKVW];   // [B*N, 3*768] : Q|K|V per row
__device__ float g_ctx[(size_t)MTOT * EMBED];  // attention output, [b,n,h,d] packed

// ---------------------------------------------------------------------------
// helpers
// ---------------------------------------------------------------------------
__device__ __forceinline__ float fexp2(float x) {
    float y;
    asm("ex2.approx.ftz.f32 %0, %1;" : "=f"(y) : "f"(x));
    return y;
}
__device__ __forceinline__ void mma_f16(float c[4],
                                        unsigned a0, unsigned a1, unsigned a2, unsigned a3,
                                        unsigned b0, unsigned b1) {
    asm volatile(
        "mma.sync.aligned.m16n8k16.row.col.f32.f16.f16.f32 "
        "{%0,%1,%2,%3}, {%4,%5,%6,%7}, {%8,%9}, {%0,%1,%2,%3};"
        : "+f"(c[0]), "+f"(c[1]), "+f"(c[2]), "+f"(c[3])
        : "r"(a0), "r"(a1), "r"(a2), "r"(a3), "r"(b0), "r"(b1));
}
__device__ __forceinline__ void ldsm4(unsigned r[4], unsigned addr) {
    asm volatile("ldmatrix.sync.aligned.m8n8.x4.shared.b16 {%0,%1,%2,%3}, [%4];"
                 : "=r"(r[0]), "=r"(r[1]), "=r"(r[2]), "=r"(r[3]) : "r"(addr));
}
__device__ __forceinline__ void ldsm4t(unsigned r[4], unsigned addr) {
    asm volatile("ldmatrix.sync.aligned.m8n8.x4.trans.shared.b16 {%0,%1,%2,%3}, [%4];"
                 : "=r"(r[0]), "=r"(r[1]), "=r"(r[2]), "=r"(r[3]) : "r"(addr));
}
__device__ __forceinline__ unsigned smem_u32(const void* p) {
    return (unsigned)__cvta_generic_to_shared(p);
}
__device__ __forceinline__ unsigned pack_h2(float lo, float hi) {
    __half2 h = __floats2half2_rn(lo, hi);
    return *reinterpret_cast<unsigned*>(&h);
}
__device__ __forceinline__ uint4 pack8(float4 v0, float4 v1) {
    uint4 r;
    r.x = pack_h2(v0.x, v0.y); r.y = pack_h2(v0.z, v0.w);
    r.z = pack_h2(v1.x, v1.y); r.w = pack_h2(v1.z, v1.w);
    return r;
}

// ---------------------------------------------------------------------------
// fp16 GEMM (NT), double-buffered, ldmatrix fragments, fp32 accumulate.
// C = A[M][K] @ B[Nn][K]^T + bias. 128x128 tile, BK=16, 256 thr, warp 64x32.
// Smem: half, row stride 24 (48B -> ldmatrix rows on 8 distinct 16B banks).
// Dynamic smem: 2 stages * 2 mats * 128*24 half * 2B = 24576 B.
// ---------------------------------------------------------------------------
#define GH   24
#define GHST (128 * GH)   // halves per matrix per stage

__global__ __launch_bounds__(256, 2) void gemm_f16_db(
    const float* __restrict__ A, const float* __restrict__ B,
    const float* __restrict__ bias, float* __restrict__ C,
    int M, int Nn, int K)
{
    extern __shared__ __half gh[];
    __half* Ah = gh;               // [2][128][24]
    __half* Bh = gh + 2 * GHST;    // [2][128][24]

    const int tid  = threadIdx.x;
    const int lane = tid & 31;
    const int warp = tid >> 5;
    const int gid  = lane >> 2;
    const int tig  = lane & 3;

    const int wm = (warp >> 2) * 64;   // 0 or 64
    const int wn = (warp & 3) * 32;    // 0,32,64,96

    const int n0 = blockIdx.x * 128;
    const int m0 = blockIdx.y * 128;

    const int lrow = tid >> 1;         // 0..127
    const int lk   = (tid & 1) * 8;    // 0 or 8 (halves)

    // ldmatrix lane offsets
    const int r16 = (lane & 7) + ((lane >> 3) & 1) * 8;   // row within 16-group
    const int ca  = (lane >> 4) * 8;                      // A col offset (0/8)
    const int cb  = ((lane >> 4) & 1) * 8;                // B col offset (0/8)

    const unsigned aBase = smem_u32(Ah) + ((wm + r16) * GH + ca) * 2;
    const unsigned bBase = smem_u32(Bh) + ((wn + r16) * GH + cb) * 2;

    float acc[4][4][4];
#pragma unroll
    for (int mi = 0; mi < 4; ++mi)
#pragma unroll
        for (int ni = 0; ni < 4; ++ni)
#pragma unroll
            for (int r = 0; r < 4; ++r) acc[mi][ni][r] = 0.0f;

    const float* Arow = A + (size_t)(m0 + lrow) * K + lk;
    const float* Brow = B + (size_t)(n0 + lrow) * K + lk;
    const int nT = K / 16;

    // prologue: tile 0 -> stage 0
    {
        float4 a0v = *(const float4*)(Arow);
        float4 a1v = *(const float4*)(Arow + 4);
        float4 b0v = *(const float4*)(Brow);
        float4 b1v = *(const float4*)(Brow + 4);
        *(uint4*)(Ah + lrow * GH + lk) = pack8(a0v, a1v);
        *(uint4*)(Bh + lrow * GH + lk) = pack8(b0v, b1v);
    }
    __syncthreads();

    for (int kt = 0; kt < nT; ++kt) {
        const int st = kt & 1;
        float4 a0v, a1v, b0v, b1v;
        if (kt + 1 < nT) {
            const int ko = (kt + 1) * 16;
            a0v = *(const float4*)(Arow + ko);
            a1v = *(const float4*)(Arow + ko + 4);
            b0v = *(const float4*)(Brow + ko);
            b1v = *(const float4*)(Brow + ko + 4);
        }

        const unsigned aS = aBase + st * (GHST * 2);
        const unsigned bS = bBase + st * (GHST * 2);
        unsigned af[4][4], bf[2][4];
#pragma unroll
        for (int mi = 0; mi < 4; ++mi)
            ldsm4(af[mi], aS + mi * (16 * GH * 2));
#pragma unroll
        for (int ng = 0; ng < 2; ++ng)
            ldsm4(bf[ng], bS + ng * (16 * GH * 2));
#pragma unroll
        for (int mi = 0; mi < 4; ++mi)
#pragma unroll
            for (int ni = 0; ni < 4; ++ni)
                mma_f16(acc[mi][ni], af[mi][0], af[mi][1], af[mi][2], af[mi][3],
                        bf[ni >> 1][ni & 1], bf[ni >> 1][(ni & 1) + 2]);

        if (kt + 1 < nT) {
            __half* Ad = Ah + (st ^ 1) * GHST;
            __half* Bd = Bh + (st ^ 1) * GHST;
            __syncthreads();
            *(uint4*)(Ad + lrow * GH + lk) = pack8(a0v, a1v);
            *(uint4*)(Bd + lrow * GH + lk) = pack8(b0v, b1v);
            __syncthreads();
        }
    }

    // Epilogue: bias + store
#pragma unroll
    for (int ni = 0; ni < 4; ++ni) {
        const int col = n0 + wn + ni * 8 + 2 * tig;
        const float bx = bias[col];
        const float by = bias[col + 1];
#pragma unroll
        for (int mi = 0; mi < 4; ++mi) {
            const int row = m0 + wm + mi * 16 + gid;
            *(float2*)(C + (size_t)row * Nn + col) =
                make_float2(acc[mi][ni][0] + bx, acc[mi][ni][1] + by);
            *(float2*)(C + (size_t)(row + 8) * Nn + col) =
                make_float2(acc[mi][ni][2] + bx, acc[mi][ni][3] + by);
        }
    }
}

// ---------------------------------------------------------------------------
// Flash attention v5: all-fp16 mma (fp32 accum). Q[128][72]h, K[64][72]h,
// V[64][72]h (all row-major [token][d]); K as direct B operand, V via
// ldmatrix.trans; P stays in registers. Smem = 256*72*2 = 36864 B.
// ---------------------------------------------------------------------------
#define AH_Q 0
#define AH_K (128 * 72)
#define AH_V (AH_K + 64 * 72)
#define ATT_BYTES ((128 + 64 + 64) * 72 * 2)

__global__ __launch_bounds__(256, 2) void attn_flash_f16()
{
    extern __shared__ __half ah[];
    __half* qh = ah + AH_Q;
    __half* kh = ah + AH_K;
    __half* vh = ah + AH_V;

    const int tid  = threadIdx.x;
    const int lane = tid & 31;
    const int warp = tid >> 5;
    const int gid  = lane >> 2;
    const int tig  = lane & 3;
    const int wm   = warp * 16;

    const int b  = blockIdx.y / NHEAD;
    const int h  = blockIdx.y % NHEAD;
    const int q0 = blockIdx.x * 128;

    // ldmatrix lane offsets
    const int r16 = (lane & 7) + ((lane >> 3) & 1) * 8;
    const int caQ = (lane >> 4) * 8;          // A pattern col
    const int cbKV = ((lane >> 4) & 1) * 8;   // B pattern col

    const unsigned qA = smem_u32(qh) + ((wm + r16) * 72 + caQ) * 2;
    const unsigned kB = smem_u32(kh) + (r16 * 72 + cbKV) * 2;
    const unsigned vB = smem_u32(vh) + (r16 * 72 + cbKV) * 2;

    // ---- load Q tile (scale*log2e folded, fp16) ----
    {
        const int qrow = tid & 127;
        const int qdh  = (tid >> 7) * 32;
        const float qs = 0.125f * 1.4426950408889634f;
        const float* src = g_qkv + (size_t)(b * NN + q0 + qrow) * QKVW + h * HDIM + qdh;
        __half* dst = qh + qrow * 72 + qdh;
#pragma unroll
        for (int u = 0; u < 4; ++u) {
            float4 v0 = *(const float4*)(src + u * 8);
            float4 v1 = *(const float4*)(src + u * 8 + 4);
            v0.x *= qs; v0.y *= qs; v0.z *= qs; v0.w *= qs;
            v1.x *= qs; v1.y *= qs; v1.z *= qs; v1.w *= qs;
            *(uint4*)(dst + u * 8) = pack8(v0, v1);
        }
    }

    // K/V loader: kr = row, sel 0,1 = K d-halves; 2,3 = V d-halves
    const int kr   = tid & 63;
    const int sel  = tid >> 6;
    const int kdh  = (sel & 1) * 32;
    const size_t kvoff = (size_t)h * HDIM + kdh + ((sel >> 1) ? 2 * EMBED : EMBED);
    __half* kvdst = ((sel >> 1) ? vh : kh) + kr * 72 + kdh;

    float4 pf[8];
    // prologue: tile 0 -> smem, prefetch tile 1 -> regs
    {
        const float* srcp = g_qkv + (size_t)(b * NN + kr) * QKVW + kvoff;
#pragma unroll
        for (int u = 0; u < 8; ++u) pf[u] = *(const float4*)(srcp + u * 4);
#pragma unroll
        for (int u = 0; u < 4; ++u)
            *(uint4*)(kvdst + u * 8) = pack8(pf[2 * u], pf[2 * u + 1]);
        const float* srcn = g_qkv + (size_t)(b * NN + 64 + kr) * QKVW + kvoff;
#pragma unroll
        for (int u = 0; u < 8; ++u) pf[u] = *(const float4*)(srcn + u * 4);
    }
    __syncthreads();

    float m0r = -1.0e30f, m1r = -1.0e30f;
    float l0 = 0.0f, l1 = 0.0f;
    float O[8][4];
#pragma unroll
    for (int ni = 0; ni < 8; ++ni)
#pragma unroll
        for (int r = 0; r < 4; ++r) O[ni][r] = 0.0f;

    const int NT = NN / 64;
    for (int kt = 0; kt < NT; ++kt) {
        // ---- S = Qhat @ K^T (fp16 mma) ----
        float s[8][4];
#pragma unroll
        for (int ni = 0; ni < 8; ++ni)
#pragma unroll
            for (int r = 0; r < 4; ++r) s[ni][r] = 0.0f;
#pragma unroll
        for (int ks = 0; ks < 4; ++ks) {          // d in 16-chunks
            unsigned aq[4];
            ldsm4(aq, qA + ks * 32);
#pragma unroll
            for (int j = 0; j < 4; ++j) {         // key 16-groups
                unsigned bk[4];
                ldsm4(bk, kB + j * (16 * 72 * 2) + ks * 32);
                mma_f16(s[2 * j],     aq[0], aq[1], aq[2], aq[3], bk[0], bk[2]);
                mma_f16(s[2 * j + 1], aq[0], aq[1], aq[2], aq[3], bk[1], bk[3]);
            }
        }

        // ---- online softmax (log2 domain) ----
        float rm0 = -1.0e30f, rm1 = -1.0e30f;
#pragma unroll
        for (int ni = 0; ni < 8; ++ni) {
            rm0 = fmaxf(rm0, fmaxf(s[ni][0], s[ni][1]));
            rm1 = fmaxf(rm1, fmaxf(s[ni][2], s[ni][3]));
        }
        rm0 = fmaxf(rm0, __shfl_xor_sync(0xffffffffu, rm0, 1));
        rm0 = fmaxf(rm0, __shfl_xor_sync(0xffffffffu, rm0, 2));
        rm1 = fmaxf(rm1, __shfl_xor_sync(0xffffffffu, rm1, 1));
        rm1 = fmaxf(rm1, __shfl_xor_sync(0xffffffffu, rm1, 2));

        const float mn0 = fmaxf(m0r, rm0);
        const float mn1 = fmaxf(m1r, rm1);
        const float al0 = fexp2(m0r - mn0);
        const float al1 = fexp2(m1r - mn1);
        m0r = mn0; m1r = mn1;

        float ps0 = 0.0f, ps1 = 0.0f;
#pragma unroll
        for (int ni = 0; ni < 8; ++ni) {
            s[ni][0] = fexp2(s[ni][0] - mn0);
            s[ni][1] = fexp2(s[ni][1] - mn0);
            s[ni][2] = fexp2(s[ni][2] - mn1);
            s[ni][3] = fexp2(s[ni][3] - mn1);
            ps0 += s[ni][0] + s[ni][1];
            ps1 += s[ni][2] + s[ni][3];
        }
        ps0 += __shfl_xor_sync(0xffffffffu, ps0, 1);
        ps0 += __shfl_xor_sync(0xffffffffu, ps0, 2);
        ps1 += __shfl_xor_sync(0xffffffffu, ps1, 1);
        ps1 += __shfl_xor_sync(0xffffffffu, ps1, 2);
        l0 = l0 * al0 + ps0;
        l1 = l1 * al1 + ps1;

#pragma unroll
        for (int ni = 0; ni < 8; ++ni) {
            O[ni][0] *= al0; O[ni][1] *= al0;
            O[ni][2] *= al1; O[ni][3] *= al1;
        }

        // ---- O += P @ V : P in registers, V via ldmatrix.trans ----
#pragma unroll
        for (int j = 0; j < 4; ++j) {             // key 16-groups (k dim)
            const unsigned a0 = pack_h2(s[2 * j][0],     s[2 * j][1]);
            const unsigned a1 = pack_h2(s[2 * j][2],     s[2 * j][3]);
            const unsigned a2 = pack_h2(s[2 * j + 1][0], s[2 * j + 1][1]);
            const unsigned a3 = pack_h2(s[2 * j + 1][2], s[2 * j + 1][3]);
#pragma unroll
            for (int p = 0; p < 4; ++p) {         // d 16-groups (n dim)
                unsigned bv[4];
                ldsm4t(bv, vB + j * (16 * 72 * 2) + p * 32);
                mma_f16(O[2 * p],     a0, a1, a2, a3, bv[0], bv[1]);
                mma_f16(O[2 * p + 1], a0, a1, a2, a3, bv[2], bv[3]);
            }
        }

        // ---- rotate: store prefetched tile, prefetch next ----
        if (kt + 1 < NT) {
            __syncthreads();
#pragma unroll
            for (int u = 0; u < 4; ++u)
                *(uint4*)(kvdst + u * 8) = pack8(pf[2 * u], pf[2 * u + 1]);
            if (kt + 2 < NT) {
                const float* srcn = g_qkv + (size_t)(b * NN + (kt + 2) * 64 + kr) * QKVW + kvoff;
#pragma unroll
                for (int u = 0; u < 8; ++u) pf[u] = *(const float4*)(srcn + u * 4);
            }
            __syncthreads();
        }
    }

    // ---- normalize and write ctx[b, q, h, d] ----
    const float inv0 = 1.0f / l0;
    const float inv1 = 1.0f / l1;
    float* dst0 = g_ctx + (size_t)(b * NN + q0 + wm + gid) * EMBED + h * HDIM;
    float* dst1 = g_ctx + (size_t)(b * NN + q0 + wm + gid + 8) * EMBED + h * HDIM;
#pragma unroll
    for (int ni = 0; ni < 8; ++ni) {
        const int col = ni * 8 + 2 * tig;
        *(float2*)(dst0 + col) = make_float2(O[ni][0] * inv0, O[ni][1] * inv0);
        *(float2*)(dst1 + col) = make_float2(O[ni][2] * inv1, O[ni][3] * inv1);
    }
}

// ---------------------------------------------------------------------------
extern "C" void kernel_launch(void* const* d_in, const int* in_sizes, int n_in,
                              void* d_out, int out_size)
{
    (void)in_sizes; (void)n_in; (void)out_size;
    const float* x     = (const float*)d_in[0];
    const float* w_qkv = (const float*)d_in[1];
    const float* b_qkv = (const float*)d_in[2];
    const float* w_out = (const float*)d_in[3];
    const float* b_out = (const float*)d_in[4];
    float* out = (float*)d_out;

    float* qkv_p; float* ctx_p;
    cudaGetSymbolAddress((void**)&qkv_p, g_qkv);
    cudaGetSymbolAddress((void**)&ctx_p, g_ctx);

    static int attrs_set = 0;
    const int gemm_smem = 4 * GHST * 2;   // 24576
    const int attn_smem = ATT_BYTES;      // 36864
    if (!attrs_set) {
        cudaFuncSetAttribute(gemm_f16_db,
                             cudaFuncAttributeMaxDynamicSharedMemorySize, gemm_smem);
        cudaFuncSetAttribute(attn_flash_f16,
                             cudaFuncAttributeMaxDynamicSharedMemorySize, attn_smem);
        attrs_set = 1;
    }

    {
        dim3 grid(QKVW / 128, MTOT / 128);
        gemm_f16_db<<<grid, 256, gemm_smem>>>(x, w_qkv, b_qkv, qkv_p, MTOT, QKVW, EMBED);
    }
    {
        dim3 grid(NN / 128, BB * NHEAD);
        attn_flash_f16<<<grid, 256, attn_smem>>>();
    }
    {
        dim3 grid(EMBED / 128, MTOT / 128);
        gemm_f16_db<<<grid, 256, gemm_smem>>>(ctx_p, w_out, b_out, out, MTOT, EMBED, EMBED);
    }
}

// round 10
// speedup vs baseline: 5.6202x; 1.3005x over previous
#include <cuda_runtime.h>
#include <cuda_fp16.h>
#include <math.h>

#define EMBED 768
#define NHEAD 12
#define HDIM  64
#define BB    4
#define NN    2048
#define MTOT  (BB * NN)          // 8192
#define QKVW  (3 * EMBED)        // 2304

// Scratch (allocation-free rule: __device__ globals)
__device__ __half g_xh[(size_t)MTOT * EMBED];      // x in fp16
__device__ __half g_wqkvh[(size_t)QKVW * EMBED];   // w_qkv fp16 (Q rows pre-scaled)
__device__ __half g_wouth[(size_t)EMBED * EMBED];  // w_out fp16
__device__ __half g_qkvh[(size_t)MTOT * QKVW];     // qkv (Q pre-scaled, log2 domain)
__device__ __half g_ctxh[(size_t)MTOT * EMBED];    // attention output fp16

#define QSCALE (0.125f * 1.4426950408889634f)      // 1/sqrt(64) * log2(e)

// ---------------------------------------------------------------------------
// helpers
// ---------------------------------------------------------------------------
__device__ __forceinline__ float fexp2(float x) {
    float y;
    asm("ex2.approx.ftz.f32 %0, %1;" : "=f"(y) : "f"(x));
    return y;
}
__device__ __forceinline__ void mma_f16(float c[4],
                                        unsigned a0, unsigned a1, unsigned a2, unsigned a3,
                                        unsigned b0, unsigned b1) {
    asm volatile(
        "mma.sync.aligned.m16n8k16.row.col.f32.f16.f16.f32 "
        "{%0,%1,%2,%3}, {%4,%5,%6,%7}, {%8,%9}, {%0,%1,%2,%3};"
        : "+f"(c[0]), "+f"(c[1]), "+f"(c[2]), "+f"(c[3])
        : "r"(a0), "r"(a1), "r"(a2), "r"(a3), "r"(b0), "r"(b1));
}
__device__ __forceinline__ void ldsm4(unsigned r[4], unsigned addr) {
    asm volatile("ldmatrix.sync.aligned.m8n8.x4.shared.b16 {%0,%1,%2,%3}, [%4];"
                 : "=r"(r[0]), "=r"(r[1]), "=r"(r[2]), "=r"(r[3]) : "r"(addr));
}
__device__ __forceinline__ void ldsm4t(unsigned r[4], unsigned addr) {
    asm volatile("ldmatrix.sync.aligned.m8n8.x4.trans.shared.b16 {%0,%1,%2,%3}, [%4];"
                 : "=r"(r[0]), "=r"(r[1]), "=r"(r[2]), "=r"(r[3]) : "r"(addr));
}
__device__ __forceinline__ unsigned smem_u32(const void* p) {
    return (unsigned)__cvta_generic_to_shared(p);
}
__device__ __forceinline__ unsigned pack_h2(float lo, float hi) {
    __half2 h = __floats2half2_rn(lo, hi);
    return *reinterpret_cast<unsigned*>(&h);
}

// ---------------------------------------------------------------------------
// fp32 -> fp16 conversion (first scaleEnd elements multiplied by scale)
// ---------------------------------------------------------------------------
__global__ void conv_f2h(const float* __restrict__ src, __half* __restrict__ dst,
                         int n, int scaleEnd, float scale)
{
    int i = (blockIdx.x * blockDim.x + threadIdx.x) * 4;
    if (i >= n) return;
    float4 v = *(const float4*)(src + i);
    if (i < scaleEnd) { v.x *= scale; v.y *= scale; v.z *= scale; v.w *= scale; }
    uint2 o;
    o.x = pack_h2(v.x, v.y);
    o.y = pack_h2(v.z, v.w);
    *(uint2*)(dst + i) = o;
}

// ---------------------------------------------------------------------------
// fp16 GEMM (NT), BK=32, double-buffered, ldmatrix, fp32 accumulate.
// C = A[M][K] @ B[Nn][K]^T + bias (bias cols < scaleEnd multiplied by bscale).
// 128x128 tile, 256 thr (8 warps), warp 64x32.
// Smem: half rows of stride 40. Loader: 2 thr/row, 2 uint4 each (32 halves).
// Dynamic smem: 2 stages * 2 mats * 128*40 * 2B = 40960 B.
// ---------------------------------------------------------------------------
#define GH   40
#define GHST (128 * GH)   // halves per matrix per stage

template <bool HALF_OUT>
__global__ __launch_bounds__(256, 2) void gemm_h_db(
    const __half* __restrict__ A, const __half* __restrict__ B,
    const float* __restrict__ bias, void* __restrict__ Cv,
    int M, int Nn, int K, int scaleEnd, float bscale)
{
    extern __shared__ __half gh[];
    __half* Ah = gh;               // [2][128][40]
    __half* Bh = gh + 2 * GHST;    // [2][128][40]

    const int tid  = threadIdx.x;
    const int lane = tid & 31;
    const int warp = tid >> 5;
    const int gid  = lane >> 2;
    const int tig  = lane & 3;

    const int wm = (warp >> 2) * 64;   // 0 or 64
    const int wn = (warp & 3) * 32;    // 0,32,64,96

    const int n0 = blockIdx.x * 128;
    const int m0 = blockIdx.y * 128;

    const int lrow = tid >> 1;         // 0..127
    const int lk   = (tid & 1) * 16;   // 0 or 16 (halves)

    // ldmatrix lane offsets
    const int r16 = (lane & 7) + ((lane >> 3) & 1) * 8;
    const int ca  = (lane >> 4) * 8;
    const int cb  = ((lane >> 4) & 1) * 8;

    const unsigned aBase = smem_u32(Ah) + ((wm + r16) * GH + ca) * 2;
    const unsigned bBase = smem_u32(Bh) + ((wn + r16) * GH + cb) * 2;

    float acc[4][4][4];
#pragma unroll
    for (int mi = 0; mi < 4; ++mi)
#pragma unroll
        for (int ni = 0; ni < 4; ++ni)
#pragma unroll
            for (int r = 0; r < 4; ++r) acc[mi][ni][r] = 0.0f;

    const __half* Arow = A + (size_t)(m0 + lrow) * K + lk;
    const __half* Brow = B + (size_t)(n0 + lrow) * K + lk;
    const int nT = K / 32;

    // prologue: full 32-half rows (2 x uint4 per thread)
    {
        *(uint4*)(Ah + lrow * GH + lk)     = *(const uint4*)(Arow);
        *(uint4*)(Ah + lrow * GH + lk + 8) = *(const uint4*)(Arow + 8);
        *(uint4*)(Bh + lrow * GH + lk)     = *(const uint4*)(Brow);
        *(uint4*)(Bh + lrow * GH + lk + 8) = *(const uint4*)(Brow + 8);
    }
    __syncthreads();

    for (int kt = 0; kt < nT; ++kt) {
        const int st = kt & 1;
        uint4 av0, av1, bv0, bv1;
        if (kt + 1 < nT) {
            const int ko = (kt + 1) * 32;
            av0 = *(const uint4*)(Arow + ko);
            av1 = *(const uint4*)(Arow + ko + 8);
            bv0 = *(const uint4*)(Brow + ko);
            bv1 = *(const uint4*)(Brow + ko + 8);
        }

        const unsigned aS = aBase + st * (GHST * 2);
        const unsigned bS = bBase + st * (GHST * 2);
#pragma unroll
        for (int ks = 0; ks < 2; ++ks) {
            const unsigned koff = ks * 32;   // 16 halves
            unsigned af[4][4], bf[2][4];
#pragma unroll
            for (int mi = 0; mi < 4; ++mi)
                ldsm4(af[mi], aS + mi * (16 * GH * 2) + koff);
#pragma unroll
            for (int ng = 0; ng < 2; ++ng)
                ldsm4(bf[ng], bS + ng * (16 * GH * 2) + koff);
#pragma unroll
            for (int mi = 0; mi < 4; ++mi)
#pragma unroll
                for (int ni = 0; ni < 4; ++ni)
                    mma_f16(acc[mi][ni], af[mi][0], af[mi][1], af[mi][2], af[mi][3],
                            bf[ni >> 1][ni & 1], bf[ni >> 1][(ni & 1) + 2]);
        }

        if (kt + 1 < nT) {
            __half* Ad = Ah + (st ^ 1) * GHST;
            __half* Bd = Bh + (st ^ 1) * GHST;
            __syncthreads();
            *(uint4*)(Ad + lrow * GH + lk)     = av0;
            *(uint4*)(Ad + lrow * GH + lk + 8) = av1;
            *(uint4*)(Bd + lrow * GH + lk)     = bv0;
            *(uint4*)(Bd + lrow * GH + lk + 8) = bv1;
            __syncthreads();
        }
    }

    // Epilogue: bias (+optional scale) then store fp16 or fp32
#pragma unroll
    for (int ni = 0; ni < 4; ++ni) {
        const int col = n0 + wn + ni * 8 + 2 * tig;
        const float bs = (col < scaleEnd) ? bscale : 1.0f;
        const float bx = bias[col] * bs;
        const float by = bias[col + 1] * bs;
#pragma unroll
        for (int mi = 0; mi < 4; ++mi) {
            const int row = m0 + wm + mi * 16 + gid;
            if (HALF_OUT) {
                __half* C = (__half*)Cv;
                *(unsigned*)(C + (size_t)row * Nn + col) =
                    pack_h2(acc[mi][ni][0] + bx, acc[mi][ni][1] + by);
                *(unsigned*)(C + (size_t)(row + 8) * Nn + col) =
                    pack_h2(acc[mi][ni][2] + bx, acc[mi][ni][3] + by);
            } else {
                float* C = (float*)Cv;
                *(float2*)(C + (size_t)row * Nn + col) =
                    make_float2(acc[mi][ni][0] + bx, acc[mi][ni][1] + by);
                *(float2*)(C + (size_t)(row + 8) * Nn + col) =
                    make_float2(acc[mi][ni][2] + bx, acc[mi][ni][3] + by);
            }
        }
    }
}

// ---------------------------------------------------------------------------
// Flash attention: all-fp16 mma (fp32 accum), fp16 gmem I/O, pure-copy loaders.
// Q[128][72]h, K[64][72]h, V[64][72]h; P stays in registers.
// Smem = 256*72*2 = 36864 B.
// ---------------------------------------------------------------------------
#define AH_Q 0
#define AH_K (128 * 72)
#define AH_V (AH_K + 64 * 72)
#define ATT_BYTES ((128 + 64 + 64) * 72 * 2)

__global__ __launch_bounds__(256, 2) void attn_flash_f16()
{
    extern __shared__ __half ah[];
    __half* qh = ah + AH_Q;
    __half* kh = ah + AH_K;
    __half* vh = ah + AH_V;

    const int tid  = threadIdx.x;
    const int lane = tid & 31;
    const int warp = tid >> 5;
    const int gid  = lane >> 2;
    const int tig  = lane & 3;
    const int wm   = warp * 16;

    const int b  = blockIdx.y / NHEAD;
    const int h  = blockIdx.y % NHEAD;
    const int q0 = blockIdx.x * 128;

    // ldmatrix lane offsets
    const int r16 = (lane & 7) + ((lane >> 3) & 1) * 8;
    const int caQ = (lane >> 4) * 8;
    const int cbKV = ((lane >> 4) & 1) * 8;

    const unsigned qA = smem_u32(qh) + ((wm + r16) * 72 + caQ) * 2;
    const unsigned kB = smem_u32(kh) + (r16 * 72 + cbKV) * 2;
    const unsigned vB = smem_u32(vh) + (r16 * 72 + cbKV) * 2;

    // ---- load Q tile (already scaled, fp16 in gmem -> pure copy) ----
    {
        const int qrow = tid & 127;
        const int qdh  = (tid >> 7) * 32;
        const __half* src = g_qkvh + (size_t)(b * NN + q0 + qrow) * QKVW + h * HDIM + qdh;
        __half* dst = qh + qrow * 72 + qdh;
        *(uint4*)(dst)      = *(const uint4*)(src);
        *(uint4*)(dst + 8)  = *(const uint4*)(src + 8);
        *(uint4*)(dst + 16) = *(const uint4*)(src + 16);
        *(uint4*)(dst + 24) = *(const uint4*)(src + 24);
    }

    // K/V loader: kr = row, sel 0,1 = K d-halves; 2,3 = V d-halves
    const int kr   = tid & 63;
    const int sel  = tid >> 6;
    const int kdh  = (sel & 1) * 32;
    const size_t kvoff = (size_t)h * HDIM + kdh + ((sel >> 1) ? 2 * EMBED : EMBED);
    __half* kvdst = ((sel >> 1) ? vh : kh) + kr * 72 + kdh;

    uint4 pf[4];
    // prologue: tile 0 -> smem, prefetch tile 1 -> regs
    {
        const __half* srcp = g_qkvh + (size_t)(b * NN + kr) * QKVW + kvoff;
#pragma unroll
        for (int u = 0; u < 4; ++u) pf[u] = *(const uint4*)(srcp + u * 8);
#pragma unroll
        for (int u = 0; u < 4; ++u) *(uint4*)(kvdst + u * 8) = pf[u];
        const __half* srcn = g_qkvh + (size_t)(b * NN + 64 + kr) * QKVW + kvoff;
#pragma unroll
        for (int u = 0; u < 4; ++u) pf[u] = *(const uint4*)(srcn + u * 8);
    }
    __syncthreads();

    float m0r = -1.0e30f, m1r = -1.0e30f;
    float l0 = 0.0f, l1 = 0.0f;
    float O[8][4];
#pragma unroll
    for (int ni = 0; ni < 8; ++ni)
#pragma unroll
        for (int r = 0; r < 4; ++r) O[ni][r] = 0.0f;

    const int NT = NN / 64;
    for (int kt = 0; kt < NT; ++kt) {
        // ---- S = Qhat @ K^T (fp16 mma) ----
        float s[8][4];
#pragma unroll
        for (int ni = 0; ni < 8; ++ni)
#pragma unroll
            for (int r = 0; r < 4; ++r) s[ni][r] = 0.0f;
#pragma unroll
        for (int ks = 0; ks < 4; ++ks) {          // d in 16-chunks
            unsigned aq[4];
            ldsm4(aq, qA + ks * 32);
#pragma unroll
            for (int j = 0; j < 4; ++j) {         // key 16-groups
                unsigned bk[4];
                ldsm4(bk, kB + j * (16 * 72 * 2) + ks * 32);
                mma_f16(s[2 * j],     aq[0], aq[1], aq[2], aq[3], bk[0], bk[2]);
                mma_f16(s[2 * j + 1], aq[0], aq[1], aq[2], aq[3], bk[1], bk[3]);
            }
        }

        // ---- online softmax (log2 domain) ----
        float rm0 = -1.0e30f, rm1 = -1.0e30f;
#pragma unroll
        for (int ni = 0; ni < 8; ++ni) {
            rm0 = fmaxf(rm0, fmaxf(s[ni][0], s[ni][1]));
            rm1 = fmaxf(rm1, fmaxf(s[ni][2], s[ni][3]));
        }
        rm0 = fmaxf(rm0, __shfl_xor_sync(0xffffffffu, rm0, 1));
        rm0 = fmaxf(rm0, __shfl_xor_sync(0xffffffffu, rm0, 2));
        rm1 = fmaxf(rm1, __shfl_xor_sync(0xffffffffu, rm1, 1));
        rm1 = fmaxf(rm1, __shfl_xor_sync(0xffffffffu, rm1, 2));

        const float mn0 = fmaxf(m0r, rm0);
        const float mn1 = fmaxf(m1r, rm1);
        const float al0 = fexp2(m0r - mn0);
        const float al1 = fexp2(m1r - mn1);
        m0r = mn0; m1r = mn1;

        float ps0 = 0.0f, ps1 = 0.0f;
#pragma unroll
        for (int ni = 0; ni < 8; ++ni) {
            s[ni][0] = fexp2(s[ni][0] - mn0);
            s[ni][1] = fexp2(s[ni][1] - mn0);
            s[ni][2] = fexp2(s[ni][2] - mn1);
            s[ni][3] = fexp2(s[ni][3] - mn1);
            ps0 += s[ni][0] + s[ni][1];
            ps1 += s[ni][2] + s[ni][3];
        }
        ps0 += __shfl_xor_sync(0xffffffffu, ps0, 1);
        ps0 += __shfl_xor_sync(0xffffffffu, ps0, 2);
        ps1 += __shfl_xor_sync(0xffffffffu, ps1, 1);
        ps1 += __shfl_xor_sync(0xffffffffu, ps1, 2);
        l0 = l0 * al0 + ps0;
        l1 = l1 * al1 + ps1;

#pragma unroll
        for (int ni = 0; ni < 8; ++ni) {
            O[ni][0] *= al0; O[ni][1] *= al0;
            O[ni][2] *= al1; O[ni][3] *= al1;
        }

        // ---- O += P @ V : P in registers, V via ldmatrix.trans ----
#pragma unroll
        for (int j = 0; j < 4; ++j) {             // key 16-groups (k dim)
            const unsigned a0 = pack_h2(s[2 * j][0],     s[2 * j][1]);
            const unsigned a1 = pack_h2(s[2 * j][2],     s[2 * j][3]);
            const unsigned a2 = pack_h2(s[2 * j + 1][0], s[2 * j + 1][1]);
            const unsigned a3 = pack_h2(s[2 * j + 1][2], s[2 * j + 1][3]);
#pragma unroll
            for (int p = 0; p < 4; ++p) {         // d 16-groups (n dim)
                unsigned bv[4];
                ldsm4t(bv, vB + j * (16 * 72 * 2) + p * 32);
                mma_f16(O[2 * p],     a0, a1, a2, a3, bv[0], bv[1]);
                mma_f16(O[2 * p + 1], a0, a1, a2, a3, bv[2], bv[3]);
            }
        }

        // ---- rotate: store prefetched tile, prefetch next ----
        if (kt + 1 < NT) {
            __syncthreads();
#pragma unroll
            for (int u = 0; u < 4; ++u) *(uint4*)(kvdst + u * 8) = pf[u];
            if (kt + 2 < NT) {
                const __half* srcn = g_qkvh + (size_t)(b * NN + (kt + 2) * 64 + kr) * QKVW + kvoff;
#pragma unroll
                for (int u = 0; u < 4; ++u) pf[u] = *(const uint4*)(srcn + u * 8);
            }
            __syncthreads();
        }
    }

    // ---- normalize and write ctx (fp16) ----
    const float inv0 = 1.0f / l0;
    const float inv1 = 1.0f / l1;
    __half* dst0 = g_ctxh + (size_t)(b * NN + q0 + wm + gid) * EMBED + h * HDIM;
    __half* dst1 = g_ctxh + (size_t)(b * NN + q0 + wm + gid + 8) * EMBED + h * HDIM;
#pragma unroll
    for (int ni = 0; ni < 8; ++ni) {
        const int col = ni * 8 + 2 * tig;
        *(unsigned*)(dst0 + col) = pack_h2(O[ni][0] * inv0, O[ni][1] * inv0);
        *(unsigned*)(dst1 + col) = pack_h2(O[ni][2] * inv1, O[ni][3] * inv1);
    }
}

// ---------------------------------------------------------------------------
extern "C" void kernel_launch(void* const* d_in, const int* in_sizes, int n_in,
                              void* d_out, int out_size)
{
    (void)in_sizes; (void)n_in; (void)out_size;
    const float* x     = (const float*)d_in[0];
    const float* w_qkv = (const float*)d_in[1];
    const float* b_qkv = (const float*)d_in[2];
    const float* w_out = (const float*)d_in[3];
    const float* b_out = (const float*)d_in[4];
    float* out = (float*)d_out;

    __half *xh, *wqkvh, *wouth, *qkvh, *ctxh;
    cudaGetSymbolAddress((void**)&xh,    g_xh);
    cudaGetSymbolAddress((void**)&wqkvh, g_wqkvh);
    cudaGetSymbolAddress((void**)&wouth, g_wouth);
    cudaGetSymbolAddress((void**)&qkvh,  g_qkvh);
    cudaGetSymbolAddress((void**)&ctxh,  g_ctxh);

    const int gemm_smem = 4 * GHST * 2;   // 40960
    const int attn_smem = ATT_BYTES;      // 36864

    // 0) fp32 -> fp16 conversions (Q rows of w_qkv pre-scaled by QSCALE)
    {
        const int n1 = MTOT * EMBED;
        conv_f2h<<<n1 / 4 / 256, 256>>>(x, xh, n1, 0, 1.0f);
        const int n2 = QKVW * EMBED;
        conv_f2h<<<n2 / 4 / 256, 256>>>(w_qkv, wqkvh, n2, EMBED * EMBED, QSCALE);
        const int n3 = EMBED * EMBED;
        conv_f2h<<<n3 / 4 / 256, 256>>>(w_out, wouth, n3, 0, 1.0f);
    }

    // 1) QKV projection (half in, half out; Q bias scaled in epilogue)
    {
        dim3 grid(QKVW / 128, MTOT / 128);
        gemm_h_db<true><<<grid, 256, gemm_smem>>>(xh, wqkvh, b_qkv, qkvh,
                                                  MTOT, QKVW, EMBED, EMBED, QSCALE);
    }

    // 2) Flash attention (all fp16 I/O)
    {
        dim3 grid(NN / 128, BB * NHEAD);
        attn_flash_f16<<<grid, 256, attn_smem>>>();
    }

    // 3) Output projection (half in, fp32 out + bias)
    {
        dim3 grid(EMBED / 128, MTOT / 128);
        gemm_h_db<false><<<grid, 256, gemm_smem>>>(ctxh, wouth, b_out, out,
                                                   MTOT, EMBED, EMBED, 0, 1.0f);
    }
}